// round 13
// baseline (speedup 1.0000x reference)
#include <cuda_runtime.h>
#include <cuda_bf16.h>
#include <cstdint>

// Problem constants
#define T_ 15
#define CIN 6
#define HH 160
#define WW 160
#define F1 30
#define K1 5
#define THR1 15.0f
#define F2 250
#define K2 3
#define THR2 10.0f
#define KWTA 8
#define RADIUS 1
#define PH 80           // pooled H/W
#define IP 82           // padded pooled dim
#define FPAD 256        // padded channel count for layer-2 scratch
#define NHW (PH*PH)     // 6400

#define KREAL 270       // 30*3*3
#define NKS   17        // conv2 K chunks of 16
#define BSTR  140       // conv2 B row stride in words ([n][j] layout)

// conv2 dynamic smem layout (bytes) — 256f x 64px per CTA, 256 threads
#define SM2_SIN 0                 // 3000 bf16 = 6000 B (pad 6016)
#define SM2_B   6016              // 64 n x 140 words = 35840 B (also sD: 64x132 f32 = 33792)
#define SM2_TOTAL 41856

// conv1 dynamic smem layout (bytes)
#define SM1_A   0                 // 10*3*32*8 words = 30720 B
#define SM1_IN  30720             // 1440 floats = 5760 B
#define SM1_B   36480             // 80*136 words = 43520 B
#define SM1_SP  80000             // 128*32 bytes = 4096 B
#define SM1_TOTAL 84096

// -------- scratch (static device memory; no allocation at runtime) --------
__device__ __align__(16) __nv_bfloat16 g_inp2h[T_ * F1 * IP * IP];  // padded pooled spikes (bf16)
__device__ float g_pot2[(size_t)T_ * NHW * FPAD];      // layout (t, hw, f)
__device__ float g_val[NHW];
__device__ int   g_nsp[NHW];
__device__ int   g_wf[NHW];
__device__ unsigned int g_maxbits;
__device__ unsigned long long g_am[T_ * NHW];          // per (t,hw) argmax keys
// conv2 A fragments, per-lane LDG.128 layout:
// index = ((ks*3 + v)*16 + m16)*32 + lane ; 4 words = mma A frag {a0,a1,a2,a3}
__device__ uint4 g_W2A4[NKS * 3 * 16 * 32];
// conv1 weight image: [ks 10][v 3][row 32][8 words], swizzled, bf16x2 (ldmatrix path)
__device__ uint32_t g_W1A[10 * 3 * 32 * 8];

__device__ __forceinline__ uint32_t smem_u32(const void* p) {
    uint32_t a;
    asm("{ .reg .u64 t; cvta.to.shared.u64 t, %1; cvt.u32.u64 %0, t; }" : "=r"(a) : "l"(p));
    return a;
}
__device__ __forceinline__ void mma16816(float c[4], uint32_t a0, uint32_t a1,
                                         uint32_t a2, uint32_t a3,
                                         uint32_t b0, uint32_t b1)
{
    asm volatile(
        "mma.sync.aligned.m16n8k16.row.col.f32.bf16.bf16.f32 "
        "{%0,%1,%2,%3}, {%4,%5,%6,%7}, {%8,%9}, {%0,%1,%2,%3};"
        : "+f"(c[0]), "+f"(c[1]), "+f"(c[2]), "+f"(c[3])
        : "r"(a0), "r"(a1), "r"(a2), "r"(a3), "r"(b0), "r"(b1));
}
__device__ __forceinline__ void ldmx4(uint32_t r[4], uint32_t addr) {
    asm volatile("ldmatrix.sync.aligned.m8n8.x4.shared.b16 {%0,%1,%2,%3}, [%4];"
        : "=r"(r[0]), "=r"(r[1]), "=r"(r[2]), "=r"(r[3]) : "r"(addr));
}
__device__ __forceinline__ uint32_t bf16pack(float a, float b) {
    __nv_bfloat16 b0 = __float2bfloat16(a);
    __nv_bfloat16 b1 = __float2bfloat16(b);
    unsigned short s0 = *reinterpret_cast<unsigned short*>(&b0);
    unsigned short s1 = *reinterpret_cast<unsigned short*>(&b1);
    return ((uint32_t)s1 << 16) | (uint32_t)s0;
}

// ===================== prep: weight images (bf16 3-split) + g_inp2h zeroing =====================
__global__ __launch_bounds__(256) void prep_k(const float* __restrict__ W1,
                                              const float* __restrict__ W2)
{
    const int gid = blockIdx.x * 256 + threadIdx.x;
    const int NT = 136 * 256;

    // conv2 A-fragment image: 26112 uint4 entries
    if (gid < NKS * 3 * 16 * 32) {
        int lane = gid & 31;
        int m16  = (gid >> 5) & 15;
        int rem  = gid >> 9;              // ks*3 + v
        int v    = rem % 3;
        int ks   = rem / 3;
        uint32_t wds[4];
#pragma unroll
        for (int r = 0; r < 4; r++) {
            int f  = m16 * 16 + (lane >> 2) + ((r & 1) << 3);
            int kk = ks * 16 + (lane & 3) * 2 + ((r >> 1) << 3);
            float w0 = 0.f, w1 = 0.f;
            if (f < F2) {
                if (kk < KREAL)     w0 = W2[(size_t)f * KREAL + kk];
                if (kk + 1 < KREAL) w1 = W2[(size_t)f * KREAL + kk + 1];
            }
            float r0 = w0, r1 = w1;
            uint32_t pv = 0;
#pragma unroll
            for (int vv = 0; vv < 3; vv++) {
                uint32_t p = bf16pack(r0, r1);
                if (vv == v) pv = p;
                r0 -= __bfloat162float(__float2bfloat16(r0));
                r1 -= __bfloat162float(__float2bfloat16(r1));
            }
            wds[r] = pv;
        }
        g_W2A4[gid] = make_uint4(wds[0], wds[1], wds[2], wds[3]);
    }

    // conv1 weight image (3-way bf16 split), 2560 entries
    if (gid < 10 * 32 * 8) {
        int jw = gid & 7;
        int row = (gid >> 3) & 31;
        int ks = gid >> 8;
        int kp = ks * 8 + jw;
        int k0 = 2 * kp, k1 = k0 + 1;
        float w0 = 0.f, w1 = 0.f;
        if (row < F1) {
            if (k0 < 150) w0 = W1[row * 150 + k0];
            if (k1 < 150) w1 = W1[row * 150 + k1];
        }
        int jx = jw ^ (((row >> 2) & 1) << 2);
        float r0 = w0, r1 = w1;
#pragma unroll
        for (int v = 0; v < 3; v++) {
            uint32_t p = bf16pack(r0, r1);
            r0 -= __bfloat162float(__float2bfloat16(r0));
            r1 -= __bfloat162float(__float2bfloat16(r1));
            g_W1A[((ks * 3 + v) * 32 + row) * 8 + jx] = p;
        }
    }

    // zero g_inp2h (3,025,800 bf16 = 378,225 uint4)
    uint4 z4 = make_uint4(0u, 0u, 0u, 0u);
    for (int i = gid; i < 378225; i += NT)
        ((uint4*)g_inp2h)[i] = z4;
}

// ===================== conv1 via mma.sync (bf16 3-split) + fused d_out zeroing =====================
// grid (200 tiles, 15 t), block 256 (8 warps). Tile = 16x8 conv px (8x4 pooled).
__global__ __launch_bounds__(256) void conv1_mma_k(const float* __restrict__ data,
                                                   float* __restrict__ outz, int nf4)
{
    extern __shared__ char smem[];
    const uint32_t sb = smem_u32(smem);
    const int t = blockIdx.y;
    const int tile = blockIdx.x;
    const int ty0 = (tile / 20) * 16;    // conv-space origin
    const int tx0 = (tile % 20) * 8;
    const int tid = threadIdx.x;
    const int w = tid >> 5, lane = tid & 31;
    const int q = lane & 3, l4 = lane >> 2;

    // async-load conv1 weight image (30720 B)
    for (int i = tid; i < 1920; i += 256)
        asm volatile("cp.async.cg.shared.global [%0], [%1], 16;"
            :: "r"(sb + SM1_A + i * 16), "l"((const char*)g_W1A + (size_t)i * 16));
    asm volatile("cp.async.commit_group;" ::: "memory");

    // zero a slice of d_out
    {
        const float4 z = make_float4(0.f, 0.f, 0.f, 0.f);
        float4* o4 = (float4*)outz;
        for (int i = (t * 200 + tile) * 256 + tid; i < nf4; i += 200 * T_ * 256)
            o4[i] = z;
    }

    // stage input window: 6 ch x 20 rows x 12 cols
    float* sIn = (float*)(smem + SM1_IN);
    const float* dbase = data + (size_t)t * CIN * HH * WW;
    for (int i = tid; i < 1440; i += 256) {
        int c = i / 240, rr = i % 240;
        int iy = rr / 12, ix = rr % 12;
        int gy = ty0 - 2 + iy, gx = tx0 - 2 + ix;
        float v = 0.f;
        if (gy >= 0 && gy < HH && gx >= 0 && gx < WW)
            v = dbase[(c * HH + gy) * WW + gx];
        sIn[i] = v;
    }
    __syncthreads();

    // build B: [j 0..79][n 0..127], stride 136 words, 16-bit halves
    {
        int n = tid >> 1, h2 = tid & 1;
        int y = n >> 3, x = n & 7;
        unsigned short* Bh = (unsigned short*)(smem + SM1_B);
        int c0 = h2 * 3;
        for (int c = c0; c < c0 + 3; c++) {
#pragma unroll
            for (int ky = 0; ky < 5; ky++)
#pragma unroll
                for (int kx = 0; kx < 5; kx++) {
                    int k = c * 25 + ky * 5 + kx;
                    __nv_bfloat16 b = __float2bfloat16(sIn[(c * 20 + y + ky) * 12 + x + kx]);
                    Bh[((k >> 1) * 136 + n) * 2 + (k & 1)] = *(unsigned short*)&b;
                }
        }
        if (h2) {
            uint32_t* Bw = (uint32_t*)(smem + SM1_B);
#pragma unroll
            for (int j = 75; j < 80; j++) Bw[j * 136 + n] = 0u;   // k=150..159 pad
        }
    }
    asm volatile("cp.async.wait_group 0;" ::: "memory");
    __syncthreads();

    // fragment addressing
    const uint32_t* Bp = (const uint32_t*)(smem + SM1_B);
    const int n0 = w * 16;
    const int boff = q * 136 + n0 + l4;
    const int row_l = lane & 15;
    const uint32_t a_off = (uint32_t)(row_l * 8 +
                          ((((lane >> 4) << 2) ^ (((row_l >> 2) & 1) << 2)))) * 4;
    const uint32_t aBase = sb + SM1_A + a_off;

    float acc[2][2][4];
#pragma unroll
    for (int mf = 0; mf < 2; mf++)
#pragma unroll
        for (int nf = 0; nf < 2; nf++)
#pragma unroll
            for (int r = 0; r < 4; r++) acc[mf][nf][r] = 0.f;

#pragma unroll
    for (int ks = 0; ks < 10; ks++) {
        uint32_t b0[2], b1[2];
#pragma unroll
        for (int nf = 0; nf < 2; nf++) {
            int o = boff + ks * 8 * 136 + nf * 8;
            b0[nf] = Bp[o];
            b1[nf] = Bp[o + 4 * 136];
        }
#pragma unroll
        for (int v = 0; v < 3; v++) {
            uint32_t a0[4], a1[4];
            uint32_t ab = aBase + (uint32_t)(ks * 3 + v) * 1024;
            ldmx4(a0, ab);
            ldmx4(a1, ab + 512);
#pragma unroll
            for (int nf = 0; nf < 2; nf++) {
                mma16816(acc[0][nf], a0[0], a0[1], a0[2], a0[3], b0[nf], b1[nf]);
                mma16816(acc[1][nf], a1[0], a1[1], a1[2], a1[3], b0[nf], b1[nf]);
            }
        }
    }

    // spike bits -> smem
    unsigned char* sSp = (unsigned char*)(smem + SM1_SP);
#pragma unroll
    for (int mf = 0; mf < 2; mf++)
#pragma unroll
        for (int nf = 0; nf < 2; nf++)
#pragma unroll
            for (int r = 0; r < 4; r++) {
                int f = 16 * mf + 8 * ((r >> 1) & 1) + l4;
                int px = n0 + 8 * nf + 2 * q + (r & 1);
                sSp[px * 32 + f] = (acc[mf][nf][r] > THR1) ? 1 : 0;
            }
    __syncthreads();

    // 2x2 max-pool (OR of spike bits) -> g_inp2h (bf16)
    for (int i = tid; i < 960; i += 256) {
        int f = i >> 5, pr = i & 31;
        int pyl = pr >> 2, pxl = pr & 3;
        int p00 = ((2 * pyl) * 8 + 2 * pxl) * 32 + f;
        unsigned char s = sSp[p00] | sSp[p00 + 32] | sSp[p00 + 256] | sSp[p00 + 288];
        g_inp2h[((t * F1 + f) * IP + (ty0 / 2 + pyl + 1)) * IP + (tx0 / 2 + pxl + 1)] =
            __float2bfloat16((float)s);
    }
}

// ===================== zero_k: g_am + g_maxbits (3rd launch -> conv2 captured) ==========
__global__ __launch_bounds__(256) void zero_k()
{
    int i = blockIdx.x * 256 + threadIdx.x;
    if (i < T_ * NHW) g_am[i] = 0ull;
    if (i == 0) g_maxbits = 0u;
}

// ===================== conv2: mma.sync bf16 3-split, 256f x 64px, 256 threads ==========
// A frags LDG.128 from global; B frags via ldmatrix.x4 from [n][j] smem (barrier-free loop).
// grid (100 tiles, 15 t), block 256 (8 warps, warp tile 32f x 64px, m0 = w*32).
__global__ __launch_bounds__(256, 2) void conv2_mma_k()
{
    extern __shared__ char smem[];
    const uint32_t sb = smem_u32(smem);
    const int t = blockIdx.y;
    const int tile = blockIdx.x;
    const int ty0 = (tile / 10) * 8;
    const int tx0 = (tile % 10) * 8;
    const int tid = threadIdx.x;
    const int w = tid >> 5;
    const int lane = tid & 31;
    const int q = lane & 3, l4 = lane >> 2;

    // stage input window: 30 ch x 10 rows x 10 cols (bf16)
    unsigned short* sIn = (unsigned short*)(smem + SM2_SIN);
    const unsigned short* ib = (const unsigned short*)g_inp2h + (size_t)t * F1 * IP * IP;
    for (int i = tid; i < 3000; i += 256) {
        int c = i / 100, r = i % 100;
        sIn[i] = ib[((size_t)c * IP + (ty0 + r / 10)) * IP + (tx0 + r % 10)];
    }
    __syncthreads();

    // build B: [n 0..63][j 0..139 words] (row = pixel), 16-bit writes; 4 threads per px
    {
        int n = tid >> 2, qq = tid & 3;
        int py = n >> 3, px = n & 7;
        unsigned short* Bh = (unsigned short*)(smem + SM2_B);
        int c0 = (qq * 30) >> 2;
        int c1 = ((qq + 1) * 30) >> 2;
        for (int c = c0; c < c1; c++) {
#pragma unroll
            for (int ky = 0; ky < 3; ky++) {
#pragma unroll
                for (int kx = 0; kx < 3; kx++) {
                    int k = c * 9 + ky * 3 + kx;
                    Bh[(n * BSTR) * 2 + k] = sIn[c * 100 + (py + ky) * 10 + px + kx];
                }
            }
        }
        if (qq == 3) ((uint32_t*)(smem + SM2_B))[n * BSTR + 135] = 0u;   // k=270,271 pad
    }
    __syncthreads();

    // fragment addressing: warp tile 32f x 64px, m0 = w*32
    const int m0 = w * 32;
    const int mblk0 = w * 2;
    const uint4* gA = g_W2A4;

    // ldmatrix base addresses: call g covers nf = 2g, 2g+1 (matrices: (2g,b0),(2g,b1),(2g+1,b0),(2g+1,b1))
    uint32_t baddr[4];
    {
        int mm = lane >> 3;                 // matrix index within x4
        int rloc = lane & 7;                // row within matrix
#pragma unroll
        for (int g = 0; g < 4; g++) {
            int nf = g * 2 + (mm >> 1);
            int hi = mm & 1;
            int n = nf * 8 + rloc;
            baddr[g] = sb + SM2_B + (uint32_t)(n * BSTR + hi * 4) * 4;
        }
    }

    float acc[2][8][4];
#pragma unroll
    for (int mf = 0; mf < 2; mf++)
#pragma unroll
        for (int nf = 0; nf < 8; nf++)
#pragma unroll
            for (int r = 0; r < 4; r++) acc[mf][nf][r] = 0.f;

    // preload A frags for ks=0
    uint4 cur[3][2];
#pragma unroll
    for (int v = 0; v < 3; v++)
#pragma unroll
        for (int mf = 0; mf < 2; mf++)
            cur[v][mf] = gA[((0 * 3 + v) * 16 + mblk0 + mf) * 32 + lane];

    // main loop: ks outer (B reused), v inner; barrier-free; A prefetched 1 ks ahead
    for (int ks = 0; ks < NKS; ks++) {
        uint4 nxt[3][2];
        if (ks + 1 < NKS) {
#pragma unroll
            for (int v = 0; v < 3; v++)
#pragma unroll
                for (int mf = 0; mf < 2; mf++)
                    nxt[v][mf] = gA[(((ks + 1) * 3 + v) * 16 + mblk0 + mf) * 32 + lane];
        }

        // B fragments: 4x ldmatrix.x4 -> bfr[g] = {b0[2g], b1[2g], b0[2g+1], b1[2g+1]}
        uint32_t bfr[4][4];
#pragma unroll
        for (int g = 0; g < 4; g++)
            ldmx4(bfr[g], baddr[g] + (uint32_t)ks * 32);

#pragma unroll
        for (int v = 0; v < 3; v++) {
#pragma unroll
            for (int nf = 0; nf < 8; nf++) {
                uint32_t b0 = bfr[nf >> 1][(nf & 1) * 2];
                uint32_t b1 = bfr[nf >> 1][(nf & 1) * 2 + 1];
                mma16816(acc[0][nf], cur[v][0].x, cur[v][0].y, cur[v][0].z, cur[v][0].w, b0, b1);
                mma16816(acc[1][nf], cur[v][1].x, cur[v][1].y, cur[v][1].z, cur[v][1].w, b0, b1);
            }
        }
        if (ks + 1 < NKS) {
#pragma unroll
            for (int v = 0; v < 3; v++)
#pragma unroll
                for (int mf = 0; mf < 2; mf++)
                    cur[v][mf] = nxt[v][mf];
        }
    }

    // threshold in place
#pragma unroll
    for (int mf = 0; mf < 2; mf++)
#pragma unroll
        for (int nf = 0; nf < 8; nf++)
#pragma unroll
            for (int r = 0; r < 4; r++) {
                float v = acc[mf][nf][r];
                acc[mf][nf][r] = (v > THR2) ? v : 0.f;
            }

    // per-(t,hw) argmax keys
#pragma unroll
    for (int nf = 0; nf < 8; nf++) {
#pragma unroll
        for (int lh = 0; lh < 2; lh++) {
            unsigned long long key = 0ull;
#pragma unroll
            for (int mf = 0; mf < 2; mf++)
#pragma unroll
                for (int hi = 0; hi < 2; hi++) {
                    float tv = acc[mf][nf][(hi << 1) | lh];
                    unsigned fg = (unsigned)(m0 + 16 * mf + 8 * hi + l4);
                    unsigned long long k =
                        ((unsigned long long)__float_as_uint(tv) << 32) | (255u - fg);
                    if (k > key) key = k;
                }
#pragma unroll
            for (int msk = 4; msk <= 16; msk <<= 1) {
                unsigned long long o = __shfl_xor_sync(0xffffffffu, key, msk);
                if (o > key) key = o;
            }
            if (l4 == 0) {
                int px = 8 * nf + 2 * q + lh;
                int hw = (ty0 + (px >> 3)) * PH + tx0 + (px & 7);
                atomicMax(&g_am[t * NHW + hw], key);
            }
        }
    }

    __syncthreads();   // all B reads done; reuse SM2_B as transpose buffer

    // epilogue: two f-passes through sD [64 px][stride 132]
    float* sD = (float*)(smem + SM2_B);
#pragma unroll
    for (int pass = 0; pass < 2; pass++) {
        if ((w >> 2) == pass) {
            int fb = m0 - pass * 128;
#pragma unroll
            for (int mf = 0; mf < 2; mf++)
#pragma unroll
                for (int nf = 0; nf < 8; nf++)
#pragma unroll
                    for (int r = 0; r < 4; r++) {
                        int fl = fb + 16 * mf + 8 * ((r >> 1) & 1) + l4;
                        int px = 8 * nf + 2 * q + (r & 1);
                        sD[px * 132 + fl] = acc[mf][nf][r];
                    }
        }
        __syncthreads();
        {
            int pxl = tid >> 2;
            int fo = (tid & 3) * 32;
            int y = ty0 + (pxl >> 3), x = tx0 + (pxl & 7);
            float* o = g_pot2 + ((size_t)t * NHW + (size_t)(y * PH + x)) * FPAD + pass * 128 + fo;
            const float* s = sD + pxl * 132 + fo;
#pragma unroll
            for (int j = 0; j < 8; j++)
                *(float4*)(o + j * 4) = *(const float4*)(s + j * 4);
        }
        __syncthreads();
    }
}

// ===================== pointwise inhibition (key-based) + sparse scatter =====================
__global__ __launch_bounds__(128) void inhib_k(float* __restrict__ out)
{
    int hw = blockIdx.x * 128 + threadIdx.x;
    if (hw >= NHW) return;

    int S = 0;
    unsigned long long klast = 0ull;
#pragma unroll
    for (int t = 0; t < T_; t++) {
        unsigned long long k = g_am[t * NHW + hw];
        if ((k >> 32) != 0ull) S++;
        if (t == T_ - 1) klast = k;
    }
    int clamp14 = ((klast >> 32) != 0ull) ? 1 : 0;
    int ft0 = T_ - S;
    if (ft0 < 0) ft0 = 0;
    if (ft0 > T_ - 1) ft0 = T_ - 1;
    unsigned long long kf = g_am[ft0 * NHW + hw];
    int wf = 255 - (int)(kf & 0xFFFFFFFFull);

    if (clamp14) {
        float pv[T_];
        int nsp = 0;
#pragma unroll
        for (int t = 0; t < T_; t++) {
            pv[t] = g_pot2[((size_t)t * NHW + hw) * FPAD + wf];
            if (pv[t] > 0.f) nsp++;
        }
        int ft = T_ - nsp;
        if (ft < 0) ft = 0;
        if (ft > T_ - 1) ft = T_ - 1;
        float fval = pv[ft];
#pragma unroll
        for (int t = 0; t < T_; t++) {
            if (pv[t] > 0.f) {
                size_t o = ((size_t)t * F2 + wf) * NHW + hw;
                out[o] = 1.f;
                out[(size_t)T_ * F2 * NHW + o] = pv[t];
            }
        }
        g_val[hw] = fval;
        g_nsp[hw] = nsp;
        g_wf[hw]  = wf;
        if (nsp > 0) atomicMax(&g_maxbits, __float_as_uint(fval));
    } else {
        g_val[hw] = 0.f;
        g_nsp[hw] = 0;
        g_wf[hw]  = 0;
    }
}

// ===================== k-WTA =====================
__global__ __launch_bounds__(1024) void winners_k(float* __restrict__ out)
{
    const int tid = threadIdx.x;
    __shared__ unsigned long long sred[32];

    float maxval = __uint_as_float(g_maxbits);
    float v15 = 15.f * maxval;

    float tot[7];
    int key[7], fh[7], hh[7], ww[7];
#pragma unroll
    for (int k = 0; k < 7; k++) {
        int idx = tid + k * 1024;
        if (idx < NHW) {
            int nsp = g_nsp[idx];
            float val = g_val[idx];
            int f = g_wf[idx];
            tot[k] = (nsp > 0) ? (float)nsp * (val + v15) : 0.f;
            fh[k] = f;
            hh[k] = idx / PH;
            ww[k] = idx % PH;
            key[k] = f * NHW + idx;
        } else {
            tot[k] = 0.f; key[k] = 0; fh[k] = -2; hh[k] = -100; ww[k] = -100;
        }
    }

    float* wout = out + (size_t)2 * T_ * F2 * NHW;

    for (int it = 0; it < KWTA; it++) {
        unsigned long long p = 0ull;
#pragma unroll
        for (int k = 0; k < 7; k++) {
            if (tot[k] > 0.f) {
                unsigned long long pk =
                    ((unsigned long long)__float_as_uint(tot[k]) << 32) |
                    (unsigned long long)(0x7FFFFFFFu - (unsigned)key[k]);
                if (pk > p) p = pk;
            }
        }
#pragma unroll
        for (int o = 16; o > 0; o >>= 1) {
            unsigned long long qq = __shfl_down_sync(0xffffffffu, p, o);
            if (qq > p) p = qq;
        }
        int warp = tid >> 5, lane = tid & 31;
        if (lane == 0) sred[warp] = p;
        __syncthreads();
        if (warp == 0) {
            p = (lane < 32) ? sred[lane] : 0ull;
#pragma unroll
            for (int o = 16; o > 0; o >>= 1) {
                unsigned long long qq = __shfl_down_sync(0xffffffffu, p, o);
                if (qq > p) p = qq;
            }
            if (lane == 0) sred[0] = p;
        }
        __syncthreads();
        unsigned long long best = sred[0];
        __syncthreads();

        if ((best >> 32) == 0ull) {
            if (tid == 0) {
                wout[it * 3 + 0] = -1.f;
                wout[it * 3 + 1] = -1.f;
                wout[it * 3 + 2] = -1.f;
            }
            continue;
        }
        int bkey = (int)(0x7FFFFFFFu - (unsigned)(best & 0xFFFFFFFFull));
        int bf = bkey / NHW;
        int bhw = bkey % NHW;
        int bh = bhw / PH, bw = bhw % PH;

        if (tid == 0) {
            wout[it * 3 + 0] = (float)bf;
            wout[it * 3 + 1] = (float)bh;
            wout[it * 3 + 2] = (float)bw;
        }

#pragma unroll
        for (int k = 0; k < 7; k++) {
            int dh = hh[k] - bh; if (dh < 0) dh = -dh;
            int dw = ww[k] - bw; if (dw < 0) dw = -dw;
            if (fh[k] == bf || (dh <= RADIUS && dw <= RADIUS)) tot[k] = 0.f;
        }
    }
}

// ===================== launch =====================
extern "C" void kernel_launch(void* const* d_in, const int* in_sizes, int n_in,
                              void* d_out, int out_size)
{
    const float* data = (const float*)d_in[0];
    const float* W1   = (const float*)d_in[1];
    const float* W2   = (const float*)d_in[2];
    float* out = (float*)d_out;

    cudaFuncSetAttribute(conv1_mma_k, cudaFuncAttributeMaxDynamicSharedMemorySize, SM1_TOTAL);
    cudaFuncSetAttribute(conv2_mma_k, cudaFuncAttributeMaxDynamicSharedMemorySize, SM2_TOTAL);

    prep_k<<<136, 256>>>(W1, W2);

    dim3 g1(200, T_);
    conv1_mma_k<<<g1, 256, SM1_TOTAL>>>(data, out, out_size / 4);

    zero_k<<<(T_ * NHW + 255) / 256, 256>>>();

    dim3 g2(100, T_);
    conv2_mma_k<<<g2, 256, SM2_TOTAL>>>();

    inhib_k<<<(NHW + 127) / 128, 128>>>(out);

    winners_k<<<1, 1024>>>(out);
}

// round 14
// speedup vs baseline: 1.5729x; 1.5729x over previous
#include <cuda_runtime.h>
#include <cuda_bf16.h>
#include <cstdint>

// Problem constants
#define T_ 15
#define CIN 6
#define HH 160
#define WW 160
#define F1 30
#define K1 5
#define THR1 15.0f
#define F2 250
#define K2 3
#define THR2 10.0f
#define KWTA 8
#define RADIUS 1
#define PH 80           // pooled H/W
#define IP 82           // padded pooled dim
#define FPAD 256        // padded channel count for layer-2 scratch
#define NHW (PH*PH)     // 6400

#define KREAL 270       // 30*3*3
#define NKS   17        // conv2 K chunks of 16

// conv2 dynamic smem layout (bytes) — 256f x 64px per CTA, 256 threads (r12 proven)
#define SM2_SIN 0                 // 3000 bf16 = 6000 B (pad 6016)
#define SM2_B   6016              // 136 j x 72 words = 39168 B (also sD: 64x132 f32 = 33792)
#define SM2_TOTAL 45184

// conv1 dynamic smem layout (bytes) — A from global now
#define SM1_IN  0                 // 1440 bf16 = 2880 B (pad 2944)
#define SM1_B   2944              // 80 j x 136 words = 43520 B
#define SM1_SP  46464             // 128*32 bytes = 4096 B
#define SM1_TOTAL 50560

// -------- scratch (static device memory; no allocation at runtime) --------
__device__ __align__(16) __nv_bfloat16 g_inp2h[T_ * F1 * IP * IP];  // padded pooled spikes (bf16)
__device__ float g_pot2[(size_t)T_ * NHW * FPAD];      // layout (t, hw, f)
__device__ float g_val[NHW];
__device__ int   g_nsp[NHW];
__device__ int   g_wf[NHW];
__device__ unsigned int g_maxbits;
__device__ unsigned long long g_am[T_ * NHW];          // per (t,hw) argmax keys
// conv2 A fragments, per-lane LDG.128 layout:
// index = ((ks*3 + v)*16 + m16)*32 + lane ; 4 words = mma A frag {a0,a1,a2,a3}
__device__ uint4 g_W2A4[NKS * 3 * 16 * 32];
// conv1 A fragments, same per-lane layout: index = ((ks*3 + v)*2 + m16)*32 + lane
__device__ uint4 g_W1A4[10 * 3 * 2 * 32];

__device__ __forceinline__ uint32_t smem_u32(const void* p) {
    uint32_t a;
    asm("{ .reg .u64 t; cvta.to.shared.u64 t, %1; cvt.u32.u64 %0, t; }" : "=r"(a) : "l"(p));
    return a;
}
__device__ __forceinline__ void mma16816(float c[4], uint32_t a0, uint32_t a1,
                                         uint32_t a2, uint32_t a3,
                                         uint32_t b0, uint32_t b1)
{
    asm volatile(
        "mma.sync.aligned.m16n8k16.row.col.f32.bf16.bf16.f32 "
        "{%0,%1,%2,%3}, {%4,%5,%6,%7}, {%8,%9}, {%0,%1,%2,%3};"
        : "+f"(c[0]), "+f"(c[1]), "+f"(c[2]), "+f"(c[3])
        : "r"(a0), "r"(a1), "r"(a2), "r"(a3), "r"(b0), "r"(b1));
}
__device__ __forceinline__ uint32_t bf16pack(float a, float b) {
    __nv_bfloat16 b0 = __float2bfloat16(a);
    __nv_bfloat16 b1 = __float2bfloat16(b);
    unsigned short s0 = *reinterpret_cast<unsigned short*>(&b0);
    unsigned short s1 = *reinterpret_cast<unsigned short*>(&b1);
    return ((uint32_t)s1 << 16) | (uint32_t)s0;
}

// ===================== prep: weight fragment images (bf16 3-split) + g_inp2h zeroing =====================
__global__ __launch_bounds__(256) void prep_k(const float* __restrict__ W1,
                                              const float* __restrict__ W2)
{
    const int gid = blockIdx.x * 256 + threadIdx.x;
    const int NT = 136 * 256;

    // conv2 A-fragment image: 26112 uint4 entries
    if (gid < NKS * 3 * 16 * 32) {
        int lane = gid & 31;
        int m16  = (gid >> 5) & 15;
        int rem  = gid >> 9;              // ks*3 + v
        int v    = rem % 3;
        int ks   = rem / 3;
        uint32_t wds[4];
#pragma unroll
        for (int r = 0; r < 4; r++) {
            int f  = m16 * 16 + (lane >> 2) + ((r & 1) << 3);
            int kk = ks * 16 + (lane & 3) * 2 + ((r >> 1) << 3);
            float w0 = 0.f, w1 = 0.f;
            if (f < F2) {
                if (kk < KREAL)     w0 = W2[(size_t)f * KREAL + kk];
                if (kk + 1 < KREAL) w1 = W2[(size_t)f * KREAL + kk + 1];
            }
            float r0 = w0, r1 = w1;
            uint32_t pv = 0;
#pragma unroll
            for (int vv = 0; vv < 3; vv++) {
                uint32_t p = bf16pack(r0, r1);
                if (vv == v) pv = p;
                r0 -= __bfloat162float(__float2bfloat16(r0));
                r1 -= __bfloat162float(__float2bfloat16(r1));
            }
            wds[r] = pv;
        }
        g_W2A4[gid] = make_uint4(wds[0], wds[1], wds[2], wds[3]);
    }

    // conv1 A-fragment image: 1920 uint4 entries
    if (gid < 10 * 3 * 2 * 32) {
        int lane = gid & 31;
        int m16  = (gid >> 5) & 1;
        int rem  = gid >> 6;              // ks*3 + v
        int v    = rem % 3;
        int ks   = rem / 3;
        uint32_t wds[4];
#pragma unroll
        for (int r = 0; r < 4; r++) {
            int f  = m16 * 16 + (lane >> 2) + ((r & 1) << 3);
            int kk = ks * 16 + (lane & 3) * 2 + ((r >> 1) << 3);
            float w0 = 0.f, w1 = 0.f;
            if (f < F1) {
                if (kk < 150)     w0 = W1[f * 150 + kk];
                if (kk + 1 < 150) w1 = W1[f * 150 + kk + 1];
            }
            float r0 = w0, r1 = w1;
            uint32_t pv = 0;
#pragma unroll
            for (int vv = 0; vv < 3; vv++) {
                uint32_t p = bf16pack(r0, r1);
                if (vv == v) pv = p;
                r0 -= __bfloat162float(__float2bfloat16(r0));
                r1 -= __bfloat162float(__float2bfloat16(r1));
            }
            wds[r] = pv;
        }
        g_W1A4[gid] = make_uint4(wds[0], wds[1], wds[2], wds[3]);
    }

    // zero g_inp2h (3,025,800 bf16 = 378,225 uint4)
    uint4 z4 = make_uint4(0u, 0u, 0u, 0u);
    for (int i = gid; i < 378225; i += NT)
        ((uint4*)g_inp2h)[i] = z4;
}

// ===================== conv1 via mma.sync (bf16 3-split, A from global) =====================
// grid (200 tiles, 15 t), block 256 (8 warps). Tile = 16x8 conv px (8x4 pooled).
__global__ __launch_bounds__(256) void conv1_mma_k(const float* __restrict__ data,
                                                   float* __restrict__ outz, int nf4)
{
    extern __shared__ char smem[];
    const int t = blockIdx.y;
    const int tile = blockIdx.x;
    const int ty0 = (tile / 20) * 16;    // conv-space origin
    const int tx0 = (tile % 20) * 8;
    const int tid = threadIdx.x;
    const int w = tid >> 5, lane = tid & 31;
    const int q = lane & 3, l4 = lane >> 2;

    // zero a slice of d_out (fused; spare DRAM BW)
    {
        const float4 z = make_float4(0.f, 0.f, 0.f, 0.f);
        float4* o4 = (float4*)outz;
        for (int i = (t * 200 + tile) * 256 + tid; i < nf4; i += 200 * T_ * 256)
            o4[i] = z;
    }

    // stage input window as bf16 (data is exactly {0,1}): 6 ch x 20 rows x 12 cols
    unsigned short* sInH = (unsigned short*)(smem + SM1_IN);
    const float* dbase = data + (size_t)t * CIN * HH * WW;
    for (int i = tid; i < 1440; i += 256) {
        int c = i / 240, rr = i % 240;
        int iy = rr / 12, ix = rr % 12;
        int gy = ty0 - 2 + iy, gx = tx0 - 2 + ix;
        float v = 0.f;
        if (gy >= 0 && gy < HH && gx >= 0 && gx < WW)
            v = dbase[(c * HH + gy) * WW + gx];
        __nv_bfloat16 b = __float2bfloat16(v);
        sInH[i] = *(unsigned short*)&b;
    }
    __syncthreads();

    // build B: [j 0..79][n 0..127], stride 136 words, pure 16-bit copies
    {
        int n = tid >> 1, h2 = tid & 1;
        int y = n >> 3, x = n & 7;
        unsigned short* Bh = (unsigned short*)(smem + SM1_B);
        int c0 = h2 * 3;
        for (int c = c0; c < c0 + 3; c++) {
#pragma unroll
            for (int ky = 0; ky < 5; ky++)
#pragma unroll
                for (int kx = 0; kx < 5; kx++) {
                    int k = c * 25 + ky * 5 + kx;
                    Bh[((k >> 1) * 136 + n) * 2 + (k & 1)] = sInH[(c * 20 + y + ky) * 12 + x + kx];
                }
        }
        if (h2) {
            uint32_t* Bw = (uint32_t*)(smem + SM1_B);
#pragma unroll
            for (int j = 75; j < 80; j++) Bw[j * 136 + n] = 0u;   // k=150..159 pad
        }
    }
    __syncthreads();

    // fragment addressing (B from smem, A from global)
    const uint32_t* Bp = (const uint32_t*)(smem + SM1_B);
    const int n0 = w * 16;
    const int boff = q * 136 + n0 + l4;
    const uint4* gA = g_W1A4;

    float acc[2][2][4];
#pragma unroll
    for (int mf = 0; mf < 2; mf++)
#pragma unroll
        for (int nf = 0; nf < 2; nf++)
#pragma unroll
            for (int r = 0; r < 4; r++) acc[mf][nf][r] = 0.f;

    // preload A frags for ks=0
    uint4 cur[3][2];
#pragma unroll
    for (int v = 0; v < 3; v++)
#pragma unroll
        for (int mf = 0; mf < 2; mf++)
            cur[v][mf] = gA[((0 * 3 + v) * 2 + mf) * 32 + lane];

#pragma unroll
    for (int ks = 0; ks < 10; ks++) {
        uint4 nxt[3][2];
        if (ks + 1 < 10) {
#pragma unroll
            for (int v = 0; v < 3; v++)
#pragma unroll
                for (int mf = 0; mf < 2; mf++)
                    nxt[v][mf] = gA[(((ks + 1) * 3 + v) * 2 + mf) * 32 + lane];
        }

        uint32_t b0[2], b1[2];
#pragma unroll
        for (int nf = 0; nf < 2; nf++) {
            int o = boff + ks * 8 * 136 + nf * 8;
            b0[nf] = Bp[o];
            b1[nf] = Bp[o + 4 * 136];
        }
#pragma unroll
        for (int v = 0; v < 3; v++) {
#pragma unroll
            for (int nf = 0; nf < 2; nf++) {
                mma16816(acc[0][nf], cur[v][0].x, cur[v][0].y, cur[v][0].z, cur[v][0].w,
                         b0[nf], b1[nf]);
                mma16816(acc[1][nf], cur[v][1].x, cur[v][1].y, cur[v][1].z, cur[v][1].w,
                         b0[nf], b1[nf]);
            }
        }
        if (ks + 1 < 10) {
#pragma unroll
            for (int v = 0; v < 3; v++)
#pragma unroll
                for (int mf = 0; mf < 2; mf++)
                    cur[v][mf] = nxt[v][mf];
        }
    }

    // spike bits -> smem
    unsigned char* sSp = (unsigned char*)(smem + SM1_SP);
#pragma unroll
    for (int mf = 0; mf < 2; mf++)
#pragma unroll
        for (int nf = 0; nf < 2; nf++)
#pragma unroll
            for (int r = 0; r < 4; r++) {
                int f = 16 * mf + 8 * ((r >> 1) & 1) + l4;
                int px = n0 + 8 * nf + 2 * q + (r & 1);
                sSp[px * 32 + f] = (acc[mf][nf][r] > THR1) ? 1 : 0;
            }
    __syncthreads();

    // 2x2 max-pool (OR of spike bits) -> g_inp2h (bf16)
    for (int i = tid; i < 960; i += 256) {
        int f = i >> 5, pr = i & 31;
        int pyl = pr >> 2, pxl = pr & 3;
        int p00 = ((2 * pyl) * 8 + 2 * pxl) * 32 + f;
        unsigned char s = sSp[p00] | sSp[p00 + 32] | sSp[p00 + 256] | sSp[p00 + 288];
        g_inp2h[((t * F1 + f) * IP + (ty0 / 2 + pyl + 1)) * IP + (tx0 / 2 + pxl + 1)] =
            __float2bfloat16((float)s);
    }
}

// ===================== zero_k: g_am + g_maxbits (3rd launch -> conv2 captured) ==========
__global__ __launch_bounds__(256) void zero_k()
{
    int i = blockIdx.x * 256 + threadIdx.x;
    if (i < T_ * NHW) g_am[i] = 0ull;
    if (i == 0) g_maxbits = 0u;
}

// ===================== conv2: mma.sync bf16 3-split, 256f x 64px, 256 threads (r12) ==========
// A fragments LDG.128 from global (barrier-free mainloop); single CTA owns all 256 f.
// grid (100 tiles, 15 t), block 256 (8 warps, warp tile 32f x 64px, m0 = w*32).
__global__ __launch_bounds__(256, 2) void conv2_mma_k()
{
    extern __shared__ char smem[];
    const int t = blockIdx.y;
    const int tile = blockIdx.x;
    const int ty0 = (tile / 10) * 8;
    const int tx0 = (tile % 10) * 8;
    const int tid = threadIdx.x;
    const int w = tid >> 5;
    const int lane = tid & 31;
    const int q = lane & 3, l4 = lane >> 2;

    // stage input window: 30 ch x 10 rows x 10 cols (bf16)
    unsigned short* sIn = (unsigned short*)(smem + SM2_SIN);
    const unsigned short* ib = (const unsigned short*)g_inp2h + (size_t)t * F1 * IP * IP;
    for (int i = tid; i < 3000; i += 256) {
        int c = i / 100, r = i % 100;
        sIn[i] = ib[((size_t)c * IP + (ty0 + r / 10)) * IP + (tx0 + r % 10)];
    }
    __syncthreads();

    // build B: packed bf16x2 [j 0..135][n 0..63] stride 72 words; 4 threads per px
    {
        int n = tid >> 2, qq = tid & 3;
        int py = n >> 3, px = n & 7;
        unsigned short* Bh = (unsigned short*)(smem + SM2_B);
        int c0 = (qq * 30) >> 2;
        int c1 = ((qq + 1) * 30) >> 2;
        for (int c = c0; c < c1; c++) {
#pragma unroll
            for (int ky = 0; ky < 3; ky++) {
#pragma unroll
                for (int kx = 0; kx < 3; kx++) {
                    int k = c * 9 + ky * 3 + kx;
                    Bh[((k >> 1) * 72 + n) * 2 + (k & 1)] = sIn[c * 100 + (py + ky) * 10 + px + kx];
                }
            }
        }
        if (qq == 3) ((uint32_t*)(smem + SM2_B))[135 * 72 + n] = 0u;   // k=270,271 pad
    }
    __syncthreads();

    // fragment addressing: warp tile 32f x 64px, m0 = w*32
    const int m0 = w * 32;
    const int mblk0 = w * 2;
    const uint32_t* Bp = (const uint32_t*)(smem + SM2_B);
    const int boff = q * 72 + l4;
    const uint4* gA = g_W2A4;

    float acc[2][8][4];
#pragma unroll
    for (int mf = 0; mf < 2; mf++)
#pragma unroll
        for (int nf = 0; nf < 8; nf++)
#pragma unroll
            for (int r = 0; r < 4; r++) acc[mf][nf][r] = 0.f;

    // preload A frags for ks=0
    uint4 cur[3][2];
#pragma unroll
    for (int v = 0; v < 3; v++)
#pragma unroll
        for (int mf = 0; mf < 2; mf++)
            cur[v][mf] = gA[((0 * 3 + v) * 16 + mblk0 + mf) * 32 + lane];

    // main loop: ks outer (B reused), v inner; barrier-free; A prefetched 1 ks ahead
    for (int ks = 0; ks < NKS; ks++) {
        uint4 nxt[3][2];
        if (ks + 1 < NKS) {
#pragma unroll
            for (int v = 0; v < 3; v++)
#pragma unroll
                for (int mf = 0; mf < 2; mf++)
                    nxt[v][mf] = gA[(((ks + 1) * 3 + v) * 16 + mblk0 + mf) * 32 + lane];
        }

        uint32_t b0[8], b1[8];
#pragma unroll
        for (int nf = 0; nf < 8; nf++) {
            int o = boff + ks * 576 + nf * 8;
            b0[nf] = Bp[o];
            b1[nf] = Bp[o + 288];
        }
#pragma unroll
        for (int v = 0; v < 3; v++) {
#pragma unroll
            for (int nf = 0; nf < 8; nf++) {
                mma16816(acc[0][nf], cur[v][0].x, cur[v][0].y, cur[v][0].z, cur[v][0].w,
                         b0[nf], b1[nf]);
                mma16816(acc[1][nf], cur[v][1].x, cur[v][1].y, cur[v][1].z, cur[v][1].w,
                         b0[nf], b1[nf]);
            }
        }
        if (ks + 1 < NKS) {
#pragma unroll
            for (int v = 0; v < 3; v++)
#pragma unroll
                for (int mf = 0; mf < 2; mf++)
                    cur[v][mf] = nxt[v][mf];
        }
    }

    // threshold in place
#pragma unroll
    for (int mf = 0; mf < 2; mf++)
#pragma unroll
        for (int nf = 0; nf < 8; nf++)
#pragma unroll
            for (int r = 0; r < 4; r++) {
                float v = acc[mf][nf][r];
                acc[mf][nf][r] = (v > THR2) ? v : 0.f;
            }

    // per-(t,hw) argmax keys
#pragma unroll
    for (int nf = 0; nf < 8; nf++) {
#pragma unroll
        for (int lh = 0; lh < 2; lh++) {
            unsigned long long key = 0ull;
#pragma unroll
            for (int mf = 0; mf < 2; mf++)
#pragma unroll
                for (int hi = 0; hi < 2; hi++) {
                    float tv = acc[mf][nf][(hi << 1) | lh];
                    unsigned fg = (unsigned)(m0 + 16 * mf + 8 * hi + l4);
                    unsigned long long k =
                        ((unsigned long long)__float_as_uint(tv) << 32) | (255u - fg);
                    if (k > key) key = k;
                }
#pragma unroll
            for (int msk = 4; msk <= 16; msk <<= 1) {
                unsigned long long o = __shfl_xor_sync(0xffffffffu, key, msk);
                if (o > key) key = o;
            }
            if (l4 == 0) {
                int px = 8 * nf + 2 * q + lh;
                int hw = (ty0 + (px >> 3)) * PH + tx0 + (px & 7);
                atomicMax(&g_am[t * NHW + hw], key);
            }
        }
    }

    __syncthreads();   // all B reads done; reuse SM2_B as transpose buffer

    // epilogue: two f-passes through sD [64 px][stride 132]
    float* sD = (float*)(smem + SM2_B);
#pragma unroll
    for (int pass = 0; pass < 2; pass++) {
        if ((w >> 2) == pass) {
            int fb = m0 - pass * 128;
#pragma unroll
            for (int mf = 0; mf < 2; mf++)
#pragma unroll
                for (int nf = 0; nf < 8; nf++)
#pragma unroll
                    for (int r = 0; r < 4; r++) {
                        int fl = fb + 16 * mf + 8 * ((r >> 1) & 1) + l4;
                        int px = 8 * nf + 2 * q + (r & 1);
                        sD[px * 132 + fl] = acc[mf][nf][r];
                    }
        }
        __syncthreads();
        {
            int pxl = tid >> 2;
            int fo = (tid & 3) * 32;
            int y = ty0 + (pxl >> 3), x = tx0 + (pxl & 7);
            float* o = g_pot2 + ((size_t)t * NHW + (size_t)(y * PH + x)) * FPAD + pass * 128 + fo;
            const float* s = sD + pxl * 132 + fo;
#pragma unroll
            for (int j = 0; j < 8; j++)
                *(float4*)(o + j * 4) = *(const float4*)(s + j * 4);
        }
        __syncthreads();
    }
}

// ===================== pointwise inhibition (key-based) + sparse scatter =====================
__global__ __launch_bounds__(128) void inhib_k(float* __restrict__ out)
{
    int hw = blockIdx.x * 128 + threadIdx.x;
    if (hw >= NHW) return;

    int S = 0;
    unsigned long long klast = 0ull;
#pragma unroll
    for (int t = 0; t < T_; t++) {
        unsigned long long k = g_am[t * NHW + hw];
        if ((k >> 32) != 0ull) S++;
        if (t == T_ - 1) klast = k;
    }
    int clamp14 = ((klast >> 32) != 0ull) ? 1 : 0;
    int ft0 = T_ - S;
    if (ft0 < 0) ft0 = 0;
    if (ft0 > T_ - 1) ft0 = T_ - 1;
    unsigned long long kf = g_am[ft0 * NHW + hw];
    int wf = 255 - (int)(kf & 0xFFFFFFFFull);

    if (clamp14) {
        float pv[T_];
        int nsp = 0;
#pragma unroll
        for (int t = 0; t < T_; t++) {
            pv[t] = g_pot2[((size_t)t * NHW + hw) * FPAD + wf];
            if (pv[t] > 0.f) nsp++;
        }
        int ft = T_ - nsp;
        if (ft < 0) ft = 0;
        if (ft > T_ - 1) ft = T_ - 1;
        float fval = pv[ft];
#pragma unroll
        for (int t = 0; t < T_; t++) {
            if (pv[t] > 0.f) {
                size_t o = ((size_t)t * F2 + wf) * NHW + hw;
                out[o] = 1.f;
                out[(size_t)T_ * F2 * NHW + o] = pv[t];
            }
        }
        g_val[hw] = fval;
        g_nsp[hw] = nsp;
        g_wf[hw]  = wf;
        if (nsp > 0) atomicMax(&g_maxbits, __float_as_uint(fval));
    } else {
        g_val[hw] = 0.f;
        g_nsp[hw] = 0;
        g_wf[hw]  = 0;
    }
}

// ===================== k-WTA =====================
__global__ __launch_bounds__(1024) void winners_k(float* __restrict__ out)
{
    const int tid = threadIdx.x;
    __shared__ unsigned long long sred[32];

    float maxval = __uint_as_float(g_maxbits);
    float v15 = 15.f * maxval;

    float tot[7];
    int key[7], fh[7], hh[7], ww[7];
#pragma unroll
    for (int k = 0; k < 7; k++) {
        int idx = tid + k * 1024;
        if (idx < NHW) {
            int nsp = g_nsp[idx];
            float val = g_val[idx];
            int f = g_wf[idx];
            tot[k] = (nsp > 0) ? (float)nsp * (val + v15) : 0.f;
            fh[k] = f;
            hh[k] = idx / PH;
            ww[k] = idx % PH;
            key[k] = f * NHW + idx;
        } else {
            tot[k] = 0.f; key[k] = 0; fh[k] = -2; hh[k] = -100; ww[k] = -100;
        }
    }

    float* wout = out + (size_t)2 * T_ * F2 * NHW;

    for (int it = 0; it < KWTA; it++) {
        unsigned long long p = 0ull;
#pragma unroll
        for (int k = 0; k < 7; k++) {
            if (tot[k] > 0.f) {
                unsigned long long pk =
                    ((unsigned long long)__float_as_uint(tot[k]) << 32) |
                    (unsigned long long)(0x7FFFFFFFu - (unsigned)key[k]);
                if (pk > p) p = pk;
            }
        }
#pragma unroll
        for (int o = 16; o > 0; o >>= 1) {
            unsigned long long qq = __shfl_down_sync(0xffffffffu, p, o);
            if (qq > p) p = qq;
        }
        int warp = tid >> 5, lane = tid & 31;
        if (lane == 0) sred[warp] = p;
        __syncthreads();
        if (warp == 0) {
            p = (lane < 32) ? sred[lane] : 0ull;
#pragma unroll
            for (int o = 16; o > 0; o >>= 1) {
                unsigned long long qq = __shfl_down_sync(0xffffffffu, p, o);
                if (qq > p) p = qq;
            }
            if (lane == 0) sred[0] = p;
        }
        __syncthreads();
        unsigned long long best = sred[0];
        __syncthreads();

        if ((best >> 32) == 0ull) {
            if (tid == 0) {
                wout[it * 3 + 0] = -1.f;
                wout[it * 3 + 1] = -1.f;
                wout[it * 3 + 2] = -1.f;
            }
            continue;
        }
        int bkey = (int)(0x7FFFFFFFu - (unsigned)(best & 0xFFFFFFFFull));
        int bf = bkey / NHW;
        int bhw = bkey % NHW;
        int bh = bhw / PH, bw = bhw % PH;

        if (tid == 0) {
            wout[it * 3 + 0] = (float)bf;
            wout[it * 3 + 1] = (float)bh;
            wout[it * 3 + 2] = (float)bw;
        }

#pragma unroll
        for (int k = 0; k < 7; k++) {
            int dh = hh[k] - bh; if (dh < 0) dh = -dh;
            int dw = ww[k] - bw; if (dw < 0) dw = -dw;
            if (fh[k] == bf || (dh <= RADIUS && dw <= RADIUS)) tot[k] = 0.f;
        }
    }
}

// ===================== launch =====================
extern "C" void kernel_launch(void* const* d_in, const int* in_sizes, int n_in,
                              void* d_out, int out_size)
{
    const float* data = (const float*)d_in[0];
    const float* W1   = (const float*)d_in[1];
    const float* W2   = (const float*)d_in[2];
    float* out = (float*)d_out;

    cudaFuncSetAttribute(conv1_mma_k, cudaFuncAttributeMaxDynamicSharedMemorySize, SM1_TOTAL);
    cudaFuncSetAttribute(conv2_mma_k, cudaFuncAttributeMaxDynamicSharedMemorySize, SM2_TOTAL);

    prep_k<<<136, 256>>>(W1, W2);

    dim3 g1(200, T_);
    conv1_mma_k<<<g1, 256, SM1_TOTAL>>>(data, out, out_size / 4);

    zero_k<<<(T_ * NHW + 255) / 256, 256>>>();

    dim3 g2(100, T_);
    conv2_mma_k<<<g2, 256, SM2_TOTAL>>>();

    inhib_k<<<(NHW + 127) / 128, 128>>>(out);

    winners_k<<<1, 1024>>>(out);
}

// round 15
// speedup vs baseline: 1.6235x; 1.0322x over previous
#include <cuda_runtime.h>
#include <cuda_bf16.h>
#include <cstdint>

// Problem constants
#define T_ 15
#define CIN 6
#define HH 160
#define WW 160
#define F1 30
#define K1 5
#define THR1 15.0f
#define F2 250
#define K2 3
#define THR2 10.0f
#define KWTA 8
#define RADIUS 1
#define PH 80           // pooled H/W
#define IP 82           // padded pooled dim
#define FPAD 256        // padded channel count for layer-2 scratch
#define NHW (PH*PH)     // 6400

#define KREAL 270       // 30*3*3
#define NKS   17        // conv2 K chunks of 16

// conv2 dynamic smem layout (bytes) — 256f x 64px per CTA, 256 threads
#define SM2_SIN 0                 // 3000 bf16 = 6000 B (pad 6016)
#define SM2_B   6016              // 136 j x 72 words = 39168 B (also sD: 64x132 f32 = 33792)
#define SM2_TOTAL 45184

// conv1 dynamic smem layout (bytes) — A from global
#define SM1_IN  0                 // 1440 bf16 = 2880 B (pad 2944)
#define SM1_B   2944              // 80 j x 136 words = 43520 B
#define SM1_SP  46464             // 128*32 bytes = 4096 B
#define SM1_TOTAL 50560

// -------- scratch (static device memory; no allocation at runtime) --------
__device__ __align__(16) __nv_bfloat16 g_inp2h[T_ * F1 * IP * IP];  // padded pooled spikes (bf16)
__device__ float g_pot2[(size_t)T_ * NHW * FPAD];      // layout (t, hw, f)
__device__ float g_val[NHW];
__device__ int   g_nsp[NHW];
__device__ int   g_wf[NHW];
__device__ unsigned int g_maxbits;
__device__ unsigned long long g_am[T_ * NHW];          // per (t,hw) argmax keys
// conv2 A fragments, per-lane LDG.128 layout:
// index = ((ks*3 + v)*16 + m16)*32 + lane ; 4 words = mma A frag {a0,a1,a2,a3}
__device__ uint4 g_W2A4[NKS * 3 * 16 * 32];
// conv1 A fragments, same per-lane layout: index = ((ks*3 + v)*2 + m16)*32 + lane
__device__ uint4 g_W1A4[10 * 3 * 2 * 32];

__device__ __forceinline__ uint32_t smem_u32(const void* p) {
    uint32_t a;
    asm("{ .reg .u64 t; cvta.to.shared.u64 t, %1; cvt.u32.u64 %0, t; }" : "=r"(a) : "l"(p));
    return a;
}
__device__ __forceinline__ void mma16816(float c[4], uint32_t a0, uint32_t a1,
                                         uint32_t a2, uint32_t a3,
                                         uint32_t b0, uint32_t b1)
{
    asm volatile(
        "mma.sync.aligned.m16n8k16.row.col.f32.bf16.bf16.f32 "
        "{%0,%1,%2,%3}, {%4,%5,%6,%7}, {%8,%9}, {%0,%1,%2,%3};"
        : "+f"(c[0]), "+f"(c[1]), "+f"(c[2]), "+f"(c[3])
        : "r"(a0), "r"(a1), "r"(a2), "r"(a3), "r"(b0), "r"(b1));
}
__device__ __forceinline__ uint32_t bf16pack(float a, float b) {
    __nv_bfloat16 b0 = __float2bfloat16(a);
    __nv_bfloat16 b1 = __float2bfloat16(b);
    unsigned short s0 = *reinterpret_cast<unsigned short*>(&b0);
    unsigned short s1 = *reinterpret_cast<unsigned short*>(&b1);
    return ((uint32_t)s1 << 16) | (uint32_t)s0;
}

// ===================== prep: weight fragment images (bf16 3-split) + g_inp2h zeroing =====================
__global__ __launch_bounds__(256) void prep_k(const float* __restrict__ W1,
                                              const float* __restrict__ W2)
{
    const int gid = blockIdx.x * 256 + threadIdx.x;
    const int NT = 136 * 256;

    // conv2 A-fragment image: 26112 uint4 entries
    if (gid < NKS * 3 * 16 * 32) {
        int lane = gid & 31;
        int m16  = (gid >> 5) & 15;
        int rem  = gid >> 9;              // ks*3 + v
        int v    = rem % 3;
        int ks   = rem / 3;
        uint32_t wds[4];
#pragma unroll
        for (int r = 0; r < 4; r++) {
            int f  = m16 * 16 + (lane >> 2) + ((r & 1) << 3);
            int kk = ks * 16 + (lane & 3) * 2 + ((r >> 1) << 3);
            float w0 = 0.f, w1 = 0.f;
            if (f < F2) {
                if (kk < KREAL)     w0 = W2[(size_t)f * KREAL + kk];
                if (kk + 1 < KREAL) w1 = W2[(size_t)f * KREAL + kk + 1];
            }
            float r0 = w0, r1 = w1;
            uint32_t pv = 0;
#pragma unroll
            for (int vv = 0; vv < 3; vv++) {
                uint32_t p = bf16pack(r0, r1);
                if (vv == v) pv = p;
                r0 -= __bfloat162float(__float2bfloat16(r0));
                r1 -= __bfloat162float(__float2bfloat16(r1));
            }
            wds[r] = pv;
        }
        g_W2A4[gid] = make_uint4(wds[0], wds[1], wds[2], wds[3]);
    }

    // conv1 A-fragment image: 1920 uint4 entries
    if (gid < 10 * 3 * 2 * 32) {
        int lane = gid & 31;
        int m16  = (gid >> 5) & 1;
        int rem  = gid >> 6;              // ks*3 + v
        int v    = rem % 3;
        int ks   = rem / 3;
        uint32_t wds[4];
#pragma unroll
        for (int r = 0; r < 4; r++) {
            int f  = m16 * 16 + (lane >> 2) + ((r & 1) << 3);
            int kk = ks * 16 + (lane & 3) * 2 + ((r >> 1) << 3);
            float w0 = 0.f, w1 = 0.f;
            if (f < F1) {
                if (kk < 150)     w0 = W1[f * 150 + kk];
                if (kk + 1 < 150) w1 = W1[f * 150 + kk + 1];
            }
            float r0 = w0, r1 = w1;
            uint32_t pv = 0;
#pragma unroll
            for (int vv = 0; vv < 3; vv++) {
                uint32_t p = bf16pack(r0, r1);
                if (vv == v) pv = p;
                r0 -= __bfloat162float(__float2bfloat16(r0));
                r1 -= __bfloat162float(__float2bfloat16(r1));
            }
            wds[r] = pv;
        }
        g_W1A4[gid] = make_uint4(wds[0], wds[1], wds[2], wds[3]);
    }

    // zero g_inp2h (3,025,800 bf16 = 378,225 uint4)
    uint4 z4 = make_uint4(0u, 0u, 0u, 0u);
    for (int i = gid; i < 378225; i += NT)
        ((uint4*)g_inp2h)[i] = z4;
}

// ===================== conv1 via mma.sync (bf16 3-split, A from global) =====================
// grid (200 tiles, 15 t), block 256 (8 warps). Tile = 16x8 conv px (8x4 pooled).
__global__ __launch_bounds__(256) void conv1_mma_k(const float* __restrict__ data,
                                                   float* __restrict__ outz, int nf4)
{
    extern __shared__ char smem[];
    const int t = blockIdx.y;
    const int tile = blockIdx.x;
    const int ty0 = (tile / 20) * 16;    // conv-space origin
    const int tx0 = (tile % 20) * 8;
    const int tid = threadIdx.x;
    const int w = tid >> 5, lane = tid & 31;
    const int q = lane & 3, l4 = lane >> 2;

    // zero a slice of d_out (fused; spare DRAM BW)
    {
        const float4 z = make_float4(0.f, 0.f, 0.f, 0.f);
        float4* o4 = (float4*)outz;
        for (int i = (t * 200 + tile) * 256 + tid; i < nf4; i += 200 * T_ * 256)
            o4[i] = z;
    }

    // stage input window as bf16 (data is exactly {0,1}): 6 ch x 20 rows x 12 cols
    unsigned short* sInH = (unsigned short*)(smem + SM1_IN);
    const float* dbase = data + (size_t)t * CIN * HH * WW;
    for (int i = tid; i < 1440; i += 256) {
        int c = i / 240, rr = i % 240;
        int iy = rr / 12, ix = rr % 12;
        int gy = ty0 - 2 + iy, gx = tx0 - 2 + ix;
        float v = 0.f;
        if (gy >= 0 && gy < HH && gx >= 0 && gx < WW)
            v = dbase[(c * HH + gy) * WW + gx];
        __nv_bfloat16 b = __float2bfloat16(v);
        sInH[i] = *(unsigned short*)&b;
    }
    __syncthreads();

    // build B: [j 0..79][n 0..127], stride 136 words, pure 16-bit copies
    {
        int n = tid >> 1, h2 = tid & 1;
        int y = n >> 3, x = n & 7;
        unsigned short* Bh = (unsigned short*)(smem + SM1_B);
        int c0 = h2 * 3;
        for (int c = c0; c < c0 + 3; c++) {
#pragma unroll
            for (int ky = 0; ky < 5; ky++)
#pragma unroll
                for (int kx = 0; kx < 5; kx++) {
                    int k = c * 25 + ky * 5 + kx;
                    Bh[((k >> 1) * 136 + n) * 2 + (k & 1)] = sInH[(c * 20 + y + ky) * 12 + x + kx];
                }
        }
        if (h2) {
            uint32_t* Bw = (uint32_t*)(smem + SM1_B);
#pragma unroll
            for (int j = 75; j < 80; j++) Bw[j * 136 + n] = 0u;   // k=150..159 pad
        }
    }
    __syncthreads();

    // fragment addressing (B from smem, A from global)
    const uint32_t* Bp = (const uint32_t*)(smem + SM1_B);
    const int n0 = w * 16;
    const int boff = q * 136 + n0 + l4;
    const uint4* gA = g_W1A4;

    float acc[2][2][4];
#pragma unroll
    for (int mf = 0; mf < 2; mf++)
#pragma unroll
        for (int nf = 0; nf < 2; nf++)
#pragma unroll
            for (int r = 0; r < 4; r++) acc[mf][nf][r] = 0.f;

    // preload A frags for ks=0
    uint4 cur[3][2];
#pragma unroll
    for (int v = 0; v < 3; v++)
#pragma unroll
        for (int mf = 0; mf < 2; mf++)
            cur[v][mf] = gA[((0 * 3 + v) * 2 + mf) * 32 + lane];

#pragma unroll
    for (int ks = 0; ks < 10; ks++) {
        uint32_t b0[2], b1[2];
#pragma unroll
        for (int nf = 0; nf < 2; nf++) {
            int o = boff + ks * 8 * 136 + nf * 8;
            b0[nf] = Bp[o];
            b1[nf] = Bp[o + 4 * 136];
        }
#pragma unroll
        for (int v = 0; v < 3; v++) {
#pragma unroll
            for (int nf = 0; nf < 2; nf++) {
                mma16816(acc[0][nf], cur[v][0].x, cur[v][0].y, cur[v][0].z, cur[v][0].w,
                         b0[nf], b1[nf]);
                mma16816(acc[1][nf], cur[v][1].x, cur[v][1].y, cur[v][1].z, cur[v][1].w,
                         b0[nf], b1[nf]);
            }
            if (ks + 1 < 10) {
#pragma unroll
                for (int mf = 0; mf < 2; mf++)
                    cur[v][mf] = gA[(((ks + 1) * 3 + v) * 2 + mf) * 32 + lane];
            }
        }
    }

    // spike bits -> smem
    unsigned char* sSp = (unsigned char*)(smem + SM1_SP);
#pragma unroll
    for (int mf = 0; mf < 2; mf++)
#pragma unroll
        for (int nf = 0; nf < 2; nf++)
#pragma unroll
            for (int r = 0; r < 4; r++) {
                int f = 16 * mf + 8 * ((r >> 1) & 1) + l4;
                int px = n0 + 8 * nf + 2 * q + (r & 1);
                sSp[px * 32 + f] = (acc[mf][nf][r] > THR1) ? 1 : 0;
            }
    __syncthreads();

    // 2x2 max-pool (OR of spike bits) -> g_inp2h (bf16)
    for (int i = tid; i < 960; i += 256) {
        int f = i >> 5, pr = i & 31;
        int pyl = pr >> 2, pxl = pr & 3;
        int p00 = ((2 * pyl) * 8 + 2 * pxl) * 32 + f;
        unsigned char s = sSp[p00] | sSp[p00 + 32] | sSp[p00 + 256] | sSp[p00 + 288];
        g_inp2h[((t * F1 + f) * IP + (ty0 / 2 + pyl + 1)) * IP + (tx0 / 2 + pxl + 1)] =
            __float2bfloat16((float)s);
    }
}

// ===================== zero_k: g_am + g_maxbits (3rd launch -> conv2 captured) ==========
__global__ __launch_bounds__(256) void zero_k()
{
    int i = blockIdx.x * 256 + threadIdx.x;
    if (i < T_ * NHW) g_am[i] = 0ull;
    if (i == 0) g_maxbits = 0u;
}

// ===================== conv2: mma.sync bf16 3-split, 256f x 64px, 256 threads ==========
// A fragments LDG.128 from global; no double-buffer (register-pressure fix).
// grid (100 tiles, 15 t), block 256 (8 warps, warp tile 32f x 64px, m0 = w*32).
__global__ __launch_bounds__(256, 2) void conv2_mma_k()
{
    extern __shared__ char smem[];
    const int t = blockIdx.y;
    const int tile = blockIdx.x;
    const int ty0 = (tile / 10) * 8;
    const int tx0 = (tile % 10) * 8;
    const int tid = threadIdx.x;
    const int w = tid >> 5;
    const int lane = tid & 31;
    const int q = lane & 3, l4 = lane >> 2;

    // stage input window: 30 ch x 10 rows x 10 cols (bf16)
    unsigned short* sIn = (unsigned short*)(smem + SM2_SIN);
    const unsigned short* ib = (const unsigned short*)g_inp2h + (size_t)t * F1 * IP * IP;
    for (int i = tid; i < 3000; i += 256) {
        int c = i / 100, r = i % 100;
        sIn[i] = ib[((size_t)c * IP + (ty0 + r / 10)) * IP + (tx0 + r % 10)];
    }
    __syncthreads();

    // build B: packed bf16x2 [j 0..135][n 0..63] stride 72 words; 4 threads per px
    {
        int n = tid >> 2, qq = tid & 3;
        int py = n >> 3, px = n & 7;
        unsigned short* Bh = (unsigned short*)(smem + SM2_B);
        int c0 = (qq * 30) >> 2;
        int c1 = ((qq + 1) * 30) >> 2;
        for (int c = c0; c < c1; c++) {
#pragma unroll
            for (int ky = 0; ky < 3; ky++) {
#pragma unroll
                for (int kx = 0; kx < 3; kx++) {
                    int k = c * 9 + ky * 3 + kx;
                    Bh[((k >> 1) * 72 + n) * 2 + (k & 1)] = sIn[c * 100 + (py + ky) * 10 + px + kx];
                }
            }
        }
        if (qq == 3) ((uint32_t*)(smem + SM2_B))[135 * 72 + n] = 0u;   // k=270,271 pad
    }
    __syncthreads();

    // fragment addressing: warp tile 32f x 64px, m0 = w*32
    const int m0 = w * 32;
    const int mblk0 = w * 2;
    const uint32_t* Bp = (const uint32_t*)(smem + SM2_B);
    const int boff = q * 72 + l4;
    const uint4* gA = g_W2A4;

    float acc[2][8][4];
#pragma unroll
    for (int mf = 0; mf < 2; mf++)
#pragma unroll
        for (int nf = 0; nf < 8; nf++)
#pragma unroll
            for (int r = 0; r < 4; r++) acc[mf][nf][r] = 0.f;

    // preload A frags for ks=0
    uint4 cur[3][2];
#pragma unroll
    for (int v = 0; v < 3; v++)
#pragma unroll
        for (int mf = 0; mf < 2; mf++)
            cur[v][mf] = gA[((0 * 3 + v) * 16 + mblk0 + mf) * 32 + lane];

    // main loop: ks outer (B reused), v inner; barrier-free.
    // cur[v] is refilled for ks+1 right after its MMAs issue (WAR, no extra regs).
    for (int ks = 0; ks < NKS; ks++) {
        uint32_t b0[8], b1[8];
#pragma unroll
        for (int nf = 0; nf < 8; nf++) {
            int o = boff + ks * 576 + nf * 8;
            b0[nf] = Bp[o];
            b1[nf] = Bp[o + 288];
        }
#pragma unroll
        for (int v = 0; v < 3; v++) {
#pragma unroll
            for (int nf = 0; nf < 8; nf++) {
                mma16816(acc[0][nf], cur[v][0].x, cur[v][0].y, cur[v][0].z, cur[v][0].w,
                         b0[nf], b1[nf]);
                mma16816(acc[1][nf], cur[v][1].x, cur[v][1].y, cur[v][1].z, cur[v][1].w,
                         b0[nf], b1[nf]);
            }
            if (ks + 1 < NKS) {
#pragma unroll
                for (int mf = 0; mf < 2; mf++)
                    cur[v][mf] = gA[(((ks + 1) * 3 + v) * 16 + mblk0 + mf) * 32 + lane];
            }
        }
    }

    // threshold in place
#pragma unroll
    for (int mf = 0; mf < 2; mf++)
#pragma unroll
        for (int nf = 0; nf < 8; nf++)
#pragma unroll
            for (int r = 0; r < 4; r++) {
                float v = acc[mf][nf][r];
                acc[mf][nf][r] = (v > THR2) ? v : 0.f;
            }

    // per-(t,hw) argmax keys
#pragma unroll
    for (int nf = 0; nf < 8; nf++) {
#pragma unroll
        for (int lh = 0; lh < 2; lh++) {
            unsigned long long key = 0ull;
#pragma unroll
            for (int mf = 0; mf < 2; mf++)
#pragma unroll
                for (int hi = 0; hi < 2; hi++) {
                    float tv = acc[mf][nf][(hi << 1) | lh];
                    unsigned fg = (unsigned)(m0 + 16 * mf + 8 * hi + l4);
                    unsigned long long k =
                        ((unsigned long long)__float_as_uint(tv) << 32) | (255u - fg);
                    if (k > key) key = k;
                }
#pragma unroll
            for (int msk = 4; msk <= 16; msk <<= 1) {
                unsigned long long o = __shfl_xor_sync(0xffffffffu, key, msk);
                if (o > key) key = o;
            }
            if (l4 == 0) {
                int px = 8 * nf + 2 * q + lh;
                int hw = (ty0 + (px >> 3)) * PH + tx0 + (px & 7);
                atomicMax(&g_am[t * NHW + hw], key);
            }
        }
    }

    __syncthreads();   // all B reads done; reuse SM2_B as transpose buffer

    // epilogue: two f-passes through sD [64 px][stride 132]
    float* sD = (float*)(smem + SM2_B);
#pragma unroll
    for (int pass = 0; pass < 2; pass++) {
        if ((w >> 2) == pass) {
            int fb = m0 - pass * 128;
#pragma unroll
            for (int mf = 0; mf < 2; mf++)
#pragma unroll
                for (int nf = 0; nf < 8; nf++)
#pragma unroll
                    for (int r = 0; r < 4; r++) {
                        int fl = fb + 16 * mf + 8 * ((r >> 1) & 1) + l4;
                        int px = 8 * nf + 2 * q + (r & 1);
                        sD[px * 132 + fl] = acc[mf][nf][r];
                    }
        }
        __syncthreads();
        {
            int pxl = tid >> 2;
            int fo = (tid & 3) * 32;
            int y = ty0 + (pxl >> 3), x = tx0 + (pxl & 7);
            float* o = g_pot2 + ((size_t)t * NHW + (size_t)(y * PH + x)) * FPAD + pass * 128 + fo;
            const float* s = sD + pxl * 132 + fo;
#pragma unroll
            for (int j = 0; j < 8; j++)
                *(float4*)(o + j * 4) = *(const float4*)(s + j * 4);
        }
        __syncthreads();
    }
}

// ===================== pointwise inhibition (key-based) + sparse scatter =====================
__global__ __launch_bounds__(128) void inhib_k(float* __restrict__ out)
{
    int hw = blockIdx.x * 128 + threadIdx.x;
    if (hw >= NHW) return;

    int S = 0;
    unsigned long long klast = 0ull;
#pragma unroll
    for (int t = 0; t < T_; t++) {
        unsigned long long k = g_am[t * NHW + hw];
        if ((k >> 32) != 0ull) S++;
        if (t == T_ - 1) klast = k;
    }
    int clamp14 = ((klast >> 32) != 0ull) ? 1 : 0;
    int ft0 = T_ - S;
    if (ft0 < 0) ft0 = 0;
    if (ft0 > T_ - 1) ft0 = T_ - 1;
    unsigned long long kf = g_am[ft0 * NHW + hw];
    int wf = 255 - (int)(kf & 0xFFFFFFFFull);

    if (clamp14) {
        float pv[T_];
        int nsp = 0;
#pragma unroll
        for (int t = 0; t < T_; t++) {
            pv[t] = g_pot2[((size_t)t * NHW + hw) * FPAD + wf];
            if (pv[t] > 0.f) nsp++;
        }
        int ft = T_ - nsp;
        if (ft < 0) ft = 0;
        if (ft > T_ - 1) ft = T_ - 1;
        float fval = pv[ft];
#pragma unroll
        for (int t = 0; t < T_; t++) {
            if (pv[t] > 0.f) {
                size_t o = ((size_t)t * F2 + wf) * NHW + hw;
                out[o] = 1.f;
                out[(size_t)T_ * F2 * NHW + o] = pv[t];
            }
        }
        g_val[hw] = fval;
        g_nsp[hw] = nsp;
        g_wf[hw]  = wf;
        if (nsp > 0) atomicMax(&g_maxbits, __float_as_uint(fval));
    } else {
        g_val[hw] = 0.f;
        g_nsp[hw] = 0;
        g_wf[hw]  = 0;
    }
}

// ===================== k-WTA =====================
__global__ __launch_bounds__(1024) void winners_k(float* __restrict__ out)
{
    const int tid = threadIdx.x;
    __shared__ unsigned long long sred[32];

    float maxval = __uint_as_float(g_maxbits);
    float v15 = 15.f * maxval;

    float tot[7];
    int key[7], fh[7], hh[7], ww[7];
#pragma unroll
    for (int k = 0; k < 7; k++) {
        int idx = tid + k * 1024;
        if (idx < NHW) {
            int nsp = g_nsp[idx];
            float val = g_val[idx];
            int f = g_wf[idx];
            tot[k] = (nsp > 0) ? (float)nsp * (val + v15) : 0.f;
            fh[k] = f;
            hh[k] = idx / PH;
            ww[k] = idx % PH;
            key[k] = f * NHW + idx;
        } else {
            tot[k] = 0.f; key[k] = 0; fh[k] = -2; hh[k] = -100; ww[k] = -100;
        }
    }

    float* wout = out + (size_t)2 * T_ * F2 * NHW;

    for (int it = 0; it < KWTA; it++) {
        unsigned long long p = 0ull;
#pragma unroll
        for (int k = 0; k < 7; k++) {
            if (tot[k] > 0.f) {
                unsigned long long pk =
                    ((unsigned long long)__float_as_uint(tot[k]) << 32) |
                    (unsigned long long)(0x7FFFFFFFu - (unsigned)key[k]);
                if (pk > p) p = pk;
            }
        }
#pragma unroll
        for (int o = 16; o > 0; o >>= 1) {
            unsigned long long qq = __shfl_down_sync(0xffffffffu, p, o);
            if (qq > p) p = qq;
        }
        int warp = tid >> 5, lane = tid & 31;
        if (lane == 0) sred[warp] = p;
        __syncthreads();
        if (warp == 0) {
            p = (lane < 32) ? sred[lane] : 0ull;
#pragma unroll
            for (int o = 16; o > 0; o >>= 1) {
                unsigned long long qq = __shfl_down_sync(0xffffffffu, p, o);
                if (qq > p) p = qq;
            }
            if (lane == 0) sred[0] = p;
        }
        __syncthreads();
        unsigned long long best = sred[0];
        __syncthreads();

        if ((best >> 32) == 0ull) {
            if (tid == 0) {
                wout[it * 3 + 0] = -1.f;
                wout[it * 3 + 1] = -1.f;
                wout[it * 3 + 2] = -1.f;
            }
            continue;
        }
        int bkey = (int)(0x7FFFFFFFu - (unsigned)(best & 0xFFFFFFFFull));
        int bf = bkey / NHW;
        int bhw = bkey % NHW;
        int bh = bhw / PH, bw = bhw % PH;

        if (tid == 0) {
            wout[it * 3 + 0] = (float)bf;
            wout[it * 3 + 1] = (float)bh;
            wout[it * 3 + 2] = (float)bw;
        }

#pragma unroll
        for (int k = 0; k < 7; k++) {
            int dh = hh[k] - bh; if (dh < 0) dh = -dh;
            int dw = ww[k] - bw; if (dw < 0) dw = -dw;
            if (fh[k] == bf || (dh <= RADIUS && dw <= RADIUS)) tot[k] = 0.f;
        }
    }
}

// ===================== launch =====================
extern "C" void kernel_launch(void* const* d_in, const int* in_sizes, int n_in,
                              void* d_out, int out_size)
{
    const float* data = (const float*)d_in[0];
    const float* W1   = (const float*)d_in[1];
    const float* W2   = (const float*)d_in[2];
    float* out = (float*)d_out;

    cudaFuncSetAttribute(conv1_mma_k, cudaFuncAttributeMaxDynamicSharedMemorySize, SM1_TOTAL);
    cudaFuncSetAttribute(conv2_mma_k, cudaFuncAttributeMaxDynamicSharedMemorySize, SM2_TOTAL);

    prep_k<<<136, 256>>>(W1, W2);

    dim3 g1(200, T_);
    conv1_mma_k<<<g1, 256, SM1_TOTAL>>>(data, out, out_size / 4);

    zero_k<<<(T_ * NHW + 255) / 256, 256>>>();

    dim3 g2(100, T_);
    conv2_mma_k<<<g2, 256, SM2_TOTAL>>>();

    inhib_k<<<(NHW + 127) / 128, 128>>>(out);

    winners_k<<<1, 1024>>>(out);
}

// round 16
// speedup vs baseline: 1.7325x; 1.0672x over previous
#include <cuda_runtime.h>
#include <cuda_bf16.h>
#include <cstdint>

// Problem constants
#define T_ 15
#define CIN 6
#define HH 160
#define WW 160
#define F1 30
#define K1 5
#define THR1 15.0f
#define F2 250
#define K2 3
#define THR2 10.0f
#define KWTA 8
#define RADIUS 1
#define PH 80           // pooled H/W
#define IP 82           // padded pooled dim
#define NHW (PH*PH)     // 6400

#define KREAL 270       // 30*3*3
#define NKS   17        // conv2 K chunks of 16

// conv2 dynamic smem layout (bytes) — 256f x 64px per CTA, 256 threads
#define SM2_SIN 0                 // 3000 bf16 = 6000 B (pad 6016)
#define SM2_B   6016              // 136 j x 72 words = 39168 B
#define SM2_TOTAL 45184

// conv1 dynamic smem layout (bytes) — A from global
#define SM1_IN  0                 // 1440 bf16 = 2880 B (pad 2944)
#define SM1_B   2944              // 80 j x 136 words = 43520 B
#define SM1_SP  46464             // 128*32 bytes = 4096 B
#define SM1_TOTAL 50560

// -------- scratch (static device memory; no allocation at runtime) --------
__device__ __align__(16) __nv_bfloat16 g_inp2h[T_ * F1 * IP * IP];  // padded pooled spikes (bf16)
__device__ float g_val[NHW];
__device__ int   g_nsp[NHW];
__device__ int   g_wf[NHW];
__device__ unsigned int g_maxbits;
__device__ unsigned long long g_am[T_ * NHW];          // per (t,hw) argmax keys
// conv2 A fragments, per-lane LDG.128 layout:
// index = ((ks*3 + v)*16 + m16)*32 + lane ; 4 words = mma A frag {a0,a1,a2,a3}
__device__ uint4 g_W2A4[NKS * 3 * 16 * 32];
// conv1 A fragments, same per-lane layout: index = ((ks*3 + v)*2 + m16)*32 + lane
__device__ uint4 g_W1A4[10 * 3 * 2 * 32];

__device__ __forceinline__ void mma16816(float c[4], uint32_t a0, uint32_t a1,
                                         uint32_t a2, uint32_t a3,
                                         uint32_t b0, uint32_t b1)
{
    asm volatile(
        "mma.sync.aligned.m16n8k16.row.col.f32.bf16.bf16.f32 "
        "{%0,%1,%2,%3}, {%4,%5,%6,%7}, {%8,%9}, {%0,%1,%2,%3};"
        : "+f"(c[0]), "+f"(c[1]), "+f"(c[2]), "+f"(c[3])
        : "r"(a0), "r"(a1), "r"(a2), "r"(a3), "r"(b0), "r"(b1));
}
__device__ __forceinline__ uint32_t bf16pack(float a, float b) {
    __nv_bfloat16 b0 = __float2bfloat16(a);
    __nv_bfloat16 b1 = __float2bfloat16(b);
    unsigned short s0 = *reinterpret_cast<unsigned short*>(&b0);
    unsigned short s1 = *reinterpret_cast<unsigned short*>(&b1);
    return ((uint32_t)s1 << 16) | (uint32_t)s0;
}

// ===================== prep: weight fragment images (bf16 3-split) + g_inp2h zeroing =====================
__global__ __launch_bounds__(256) void prep_k(const float* __restrict__ W1,
                                              const float* __restrict__ W2)
{
    const int gid = blockIdx.x * 256 + threadIdx.x;
    const int NT = 136 * 256;

    // conv2 A-fragment image: 26112 uint4 entries
    if (gid < NKS * 3 * 16 * 32) {
        int lane = gid & 31;
        int m16  = (gid >> 5) & 15;
        int rem  = gid >> 9;              // ks*3 + v
        int v    = rem % 3;
        int ks   = rem / 3;
        uint32_t wds[4];
#pragma unroll
        for (int r = 0; r < 4; r++) {
            int f  = m16 * 16 + (lane >> 2) + ((r & 1) << 3);
            int kk = ks * 16 + (lane & 3) * 2 + ((r >> 1) << 3);
            float w0 = 0.f, w1 = 0.f;
            if (f < F2) {
                if (kk < KREAL)     w0 = W2[(size_t)f * KREAL + kk];
                if (kk + 1 < KREAL) w1 = W2[(size_t)f * KREAL + kk + 1];
            }
            float r0 = w0, r1 = w1;
            uint32_t pv = 0;
#pragma unroll
            for (int vv = 0; vv < 3; vv++) {
                uint32_t p = bf16pack(r0, r1);
                if (vv == v) pv = p;
                r0 -= __bfloat162float(__float2bfloat16(r0));
                r1 -= __bfloat162float(__float2bfloat16(r1));
            }
            wds[r] = pv;
        }
        g_W2A4[gid] = make_uint4(wds[0], wds[1], wds[2], wds[3]);
    }

    // conv1 A-fragment image: 1920 uint4 entries
    if (gid < 10 * 3 * 2 * 32) {
        int lane = gid & 31;
        int m16  = (gid >> 5) & 1;
        int rem  = gid >> 6;              // ks*3 + v
        int v    = rem % 3;
        int ks   = rem / 3;
        uint32_t wds[4];
#pragma unroll
        for (int r = 0; r < 4; r++) {
            int f  = m16 * 16 + (lane >> 2) + ((r & 1) << 3);
            int kk = ks * 16 + (lane & 3) * 2 + ((r >> 1) << 3);
            float w0 = 0.f, w1 = 0.f;
            if (f < F1) {
                if (kk < 150)     w0 = W1[f * 150 + kk];
                if (kk + 1 < 150) w1 = W1[f * 150 + kk + 1];
            }
            float r0 = w0, r1 = w1;
            uint32_t pv = 0;
#pragma unroll
            for (int vv = 0; vv < 3; vv++) {
                uint32_t p = bf16pack(r0, r1);
                if (vv == v) pv = p;
                r0 -= __bfloat162float(__float2bfloat16(r0));
                r1 -= __bfloat162float(__float2bfloat16(r1));
            }
            wds[r] = pv;
        }
        g_W1A4[gid] = make_uint4(wds[0], wds[1], wds[2], wds[3]);
    }

    // zero g_inp2h (3,025,800 bf16 = 378,225 uint4)
    uint4 z4 = make_uint4(0u, 0u, 0u, 0u);
    for (int i = gid; i < 378225; i += NT)
        ((uint4*)g_inp2h)[i] = z4;
}

// ===================== conv1 via mma.sync (bf16 3-split, A from global) =====================
// grid (200 tiles, 15 t), block 256 (8 warps). Tile = 16x8 conv px (8x4 pooled).
__global__ __launch_bounds__(256) void conv1_mma_k(const float* __restrict__ data,
                                                   float* __restrict__ outz, int nf4)
{
    extern __shared__ char smem[];
    const int t = blockIdx.y;
    const int tile = blockIdx.x;
    const int ty0 = (tile / 20) * 16;    // conv-space origin
    const int tx0 = (tile % 20) * 8;
    const int tid = threadIdx.x;
    const int w = tid >> 5, lane = tid & 31;
    const int q = lane & 3, l4 = lane >> 2;

    // zero a slice of d_out (fused; spare DRAM BW)
    {
        const float4 z = make_float4(0.f, 0.f, 0.f, 0.f);
        float4* o4 = (float4*)outz;
        for (int i = (t * 200 + tile) * 256 + tid; i < nf4; i += 200 * T_ * 256)
            o4[i] = z;
    }

    // stage input window as bf16 (data is exactly {0,1}): 6 ch x 20 rows x 12 cols
    unsigned short* sInH = (unsigned short*)(smem + SM1_IN);
    const float* dbase = data + (size_t)t * CIN * HH * WW;
    for (int i = tid; i < 1440; i += 256) {
        int c = i / 240, rr = i % 240;
        int iy = rr / 12, ix = rr % 12;
        int gy = ty0 - 2 + iy, gx = tx0 - 2 + ix;
        float v = 0.f;
        if (gy >= 0 && gy < HH && gx >= 0 && gx < WW)
            v = dbase[(c * HH + gy) * WW + gx];
        __nv_bfloat16 b = __float2bfloat16(v);
        sInH[i] = *(unsigned short*)&b;
    }
    __syncthreads();

    // build B: [j 0..79][n 0..127], stride 136 words, pure 16-bit copies
    {
        int n = tid >> 1, h2 = tid & 1;
        int y = n >> 3, x = n & 7;
        unsigned short* Bh = (unsigned short*)(smem + SM1_B);
        int c0 = h2 * 3;
        for (int c = c0; c < c0 + 3; c++) {
#pragma unroll
            for (int ky = 0; ky < 5; ky++)
#pragma unroll
                for (int kx = 0; kx < 5; kx++) {
                    int k = c * 25 + ky * 5 + kx;
                    Bh[((k >> 1) * 136 + n) * 2 + (k & 1)] = sInH[(c * 20 + y + ky) * 12 + x + kx];
                }
        }
        if (h2) {
            uint32_t* Bw = (uint32_t*)(smem + SM1_B);
#pragma unroll
            for (int j = 75; j < 80; j++) Bw[j * 136 + n] = 0u;   // k=150..159 pad
        }
    }
    __syncthreads();

    // fragment addressing (B from smem, A from global)
    const uint32_t* Bp = (const uint32_t*)(smem + SM1_B);
    const int n0 = w * 16;
    const int boff = q * 136 + n0 + l4;
    const uint4* gA = g_W1A4;

    float acc[2][2][4];
#pragma unroll
    for (int mf = 0; mf < 2; mf++)
#pragma unroll
        for (int nf = 0; nf < 2; nf++)
#pragma unroll
            for (int r = 0; r < 4; r++) acc[mf][nf][r] = 0.f;

    // preload A frags for ks=0
    uint4 cur[3][2];
#pragma unroll
    for (int v = 0; v < 3; v++)
#pragma unroll
        for (int mf = 0; mf < 2; mf++)
            cur[v][mf] = gA[((0 * 3 + v) * 2 + mf) * 32 + lane];

#pragma unroll
    for (int ks = 0; ks < 10; ks++) {
        uint32_t b0[2], b1[2];
#pragma unroll
        for (int nf = 0; nf < 2; nf++) {
            int o = boff + ks * 8 * 136 + nf * 8;
            b0[nf] = Bp[o];
            b1[nf] = Bp[o + 4 * 136];
        }
#pragma unroll
        for (int v = 0; v < 3; v++) {
#pragma unroll
            for (int nf = 0; nf < 2; nf++) {
                mma16816(acc[0][nf], cur[v][0].x, cur[v][0].y, cur[v][0].z, cur[v][0].w,
                         b0[nf], b1[nf]);
                mma16816(acc[1][nf], cur[v][1].x, cur[v][1].y, cur[v][1].z, cur[v][1].w,
                         b0[nf], b1[nf]);
            }
            if (ks + 1 < 10) {
#pragma unroll
                for (int mf = 0; mf < 2; mf++)
                    cur[v][mf] = gA[(((ks + 1) * 3 + v) * 2 + mf) * 32 + lane];
            }
        }
    }

    // spike bits -> smem
    unsigned char* sSp = (unsigned char*)(smem + SM1_SP);
#pragma unroll
    for (int mf = 0; mf < 2; mf++)
#pragma unroll
        for (int nf = 0; nf < 2; nf++)
#pragma unroll
            for (int r = 0; r < 4; r++) {
                int f = 16 * mf + 8 * ((r >> 1) & 1) + l4;
                int px = n0 + 8 * nf + 2 * q + (r & 1);
                sSp[px * 32 + f] = (acc[mf][nf][r] > THR1) ? 1 : 0;
            }
    __syncthreads();

    // 2x2 max-pool (OR of spike bits) -> g_inp2h (bf16)
    for (int i = tid; i < 960; i += 256) {
        int f = i >> 5, pr = i & 31;
        int pyl = pr >> 2, pxl = pr & 3;
        int p00 = ((2 * pyl) * 8 + 2 * pxl) * 32 + f;
        unsigned char s = sSp[p00] | sSp[p00 + 32] | sSp[p00 + 256] | sSp[p00 + 288];
        g_inp2h[((t * F1 + f) * IP + (ty0 / 2 + pyl + 1)) * IP + (tx0 / 2 + pxl + 1)] =
            __float2bfloat16((float)s);
    }
}

// ===================== zero_k: g_am + g_maxbits (3rd launch -> conv2 captured) ==========
__global__ __launch_bounds__(256) void zero_k()
{
    int i = blockIdx.x * 256 + threadIdx.x;
    if (i < T_ * NHW) g_am[i] = 0ull;
    if (i == 0) g_maxbits = 0u;
}

// ===================== conv2: mma.sync bf16 3-split, 256f x 64px, keys only ==========
// A fragments LDG.128 from global; NO pot2 store — epilogue is threshold + argmax keys.
// grid (100 tiles, 15 t), block 256 (8 warps, warp tile 32f x 64px, m0 = w*32).
__global__ __launch_bounds__(256, 2) void conv2_mma_k()
{
    extern __shared__ char smem[];
    const int t = blockIdx.y;
    const int tile = blockIdx.x;
    const int ty0 = (tile / 10) * 8;
    const int tx0 = (tile % 10) * 8;
    const int tid = threadIdx.x;
    const int w = tid >> 5;
    const int lane = tid & 31;
    const int q = lane & 3, l4 = lane >> 2;

    // stage input window: 30 ch x 10 rows x 10 cols (bf16)
    unsigned short* sIn = (unsigned short*)(smem + SM2_SIN);
    const unsigned short* ib = (const unsigned short*)g_inp2h + (size_t)t * F1 * IP * IP;
    for (int i = tid; i < 3000; i += 256) {
        int c = i / 100, r = i % 100;
        sIn[i] = ib[((size_t)c * IP + (ty0 + r / 10)) * IP + (tx0 + r % 10)];
    }
    __syncthreads();

    // build B: packed bf16x2 [j 0..135][n 0..63] stride 72 words; 4 threads per px
    {
        int n = tid >> 2, qq = tid & 3;
        int py = n >> 3, px = n & 7;
        unsigned short* Bh = (unsigned short*)(smem + SM2_B);
        int c0 = (qq * 30) >> 2;
        int c1 = ((qq + 1) * 30) >> 2;
        for (int c = c0; c < c1; c++) {
#pragma unroll
            for (int ky = 0; ky < 3; ky++) {
#pragma unroll
                for (int kx = 0; kx < 3; kx++) {
                    int k = c * 9 + ky * 3 + kx;
                    Bh[((k >> 1) * 72 + n) * 2 + (k & 1)] = sIn[c * 100 + (py + ky) * 10 + px + kx];
                }
            }
        }
        if (qq == 3) ((uint32_t*)(smem + SM2_B))[135 * 72 + n] = 0u;   // k=270,271 pad
    }
    __syncthreads();

    // fragment addressing: warp tile 32f x 64px, m0 = w*32
    const int m0 = w * 32;
    const int mblk0 = w * 2;
    const uint32_t* Bp = (const uint32_t*)(smem + SM2_B);
    const int boff = q * 72 + l4;
    const uint4* gA = g_W2A4;

    float acc[2][8][4];
#pragma unroll
    for (int mf = 0; mf < 2; mf++)
#pragma unroll
        for (int nf = 0; nf < 8; nf++)
#pragma unroll
            for (int r = 0; r < 4; r++) acc[mf][nf][r] = 0.f;

    // preload A frags for ks=0
    uint4 cur[3][2];
#pragma unroll
    for (int v = 0; v < 3; v++)
#pragma unroll
        for (int mf = 0; mf < 2; mf++)
            cur[v][mf] = gA[((0 * 3 + v) * 16 + mblk0 + mf) * 32 + lane];

    // main loop: ks outer (B reused), v inner; barrier-free.
    for (int ks = 0; ks < NKS; ks++) {
        uint32_t b0[8], b1[8];
#pragma unroll
        for (int nf = 0; nf < 8; nf++) {
            int o = boff + ks * 576 + nf * 8;
            b0[nf] = Bp[o];
            b1[nf] = Bp[o + 288];
        }
#pragma unroll
        for (int v = 0; v < 3; v++) {
#pragma unroll
            for (int nf = 0; nf < 8; nf++) {
                mma16816(acc[0][nf], cur[v][0].x, cur[v][0].y, cur[v][0].z, cur[v][0].w,
                         b0[nf], b1[nf]);
                mma16816(acc[1][nf], cur[v][1].x, cur[v][1].y, cur[v][1].z, cur[v][1].w,
                         b0[nf], b1[nf]);
            }
            if (ks + 1 < NKS) {
#pragma unroll
                for (int mf = 0; mf < 2; mf++)
                    cur[v][mf] = gA[(((ks + 1) * 3 + v) * 16 + mblk0 + mf) * 32 + lane];
            }
        }
    }

    // per-(t,hw) argmax keys (thresholded values)
#pragma unroll
    for (int nf = 0; nf < 8; nf++) {
#pragma unroll
        for (int lh = 0; lh < 2; lh++) {
            unsigned long long key = 0ull;
#pragma unroll
            for (int mf = 0; mf < 2; mf++)
#pragma unroll
                for (int hi = 0; hi < 2; hi++) {
                    float tv = acc[mf][nf][(hi << 1) | lh];
                    tv = (tv > THR2) ? tv : 0.f;
                    unsigned fg = (unsigned)(m0 + 16 * mf + 8 * hi + l4);
                    unsigned long long k =
                        ((unsigned long long)__float_as_uint(tv) << 32) | (255u - fg);
                    if (k > key) key = k;
                }
#pragma unroll
            for (int msk = 4; msk <= 16; msk <<= 1) {
                unsigned long long o = __shfl_xor_sync(0xffffffffu, key, msk);
                if (o > key) key = o;
            }
            if (l4 == 0) {
                int px = 8 * nf + 2 * q + lh;
                int hw = (ty0 + (px >> 3)) * PH + tx0 + (px & 7);
                atomicMax(&g_am[t * NHW + hw], key);
            }
        }
    }
}

// ===================== inhibition: winner recompute (fp32) + sparse scatter ==========
// one warp per hw; grid 800 x block 256.
__global__ __launch_bounds__(256) void inhib_k(const float* __restrict__ W2,
                                               float* __restrict__ out)
{
    const int gw = (blockIdx.x * 256 + threadIdx.x) >> 5;
    const int lane = threadIdx.x & 31;
    if (gw >= NHW) return;
    const int hw = gw;

    unsigned long long myk = 0ull;
    if (lane < T_) myk = g_am[lane * NHW + hw];
    unsigned mask = __ballot_sync(0xffffffffu, (myk >> 32) != 0ull);
    int S = __popc(mask & 0x7FFFu);
    int clamp14 = (mask >> 14) & 1;
    int ft0 = T_ - S;
    if (ft0 < 0) ft0 = 0;
    if (ft0 > T_ - 1) ft0 = T_ - 1;
    unsigned long long kf = __shfl_sync(0xffffffffu, myk, ft0);
    int wf = 255 - (int)(kf & 0xFFFFFFFFull);

    if (!clamp14) {
        if (lane == 0) { g_val[hw] = 0.f; g_nsp[hw] = 0; g_wf[hw] = 0; }
        return;
    }

    // per-lane weights + window offsets (k = lane + 32*i)
    const int y = hw / PH, x = hw % PH;
    float wreg[9];
    int ofs[9];
#pragma unroll
    for (int i = 0; i < 9; i++) {
        int k = lane + 32 * i;
        bool ok = (k < KREAL);
        wreg[i] = ok ? W2[(size_t)wf * KREAL + k] : 0.f;
        int c = ok ? (k / 9) : 0;
        int rem = ok ? (k % 9) : 0;
        ofs[i] = c * (IP * IP) + (y + rem / 3) * IP + (x + rem % 3);
    }

    float pvm = 0.f;  // this lane's t value (lane == t)
#pragma unroll
    for (int t = 0; t < T_; t++) {
        const unsigned short* base = (const unsigned short*)g_inp2h + (size_t)t * F1 * IP * IP;
        float s = 0.f;
#pragma unroll
        for (int i = 0; i < 9; i++)
            if (base[ofs[i]] != 0) s += wreg[i];
#pragma unroll
        for (int o = 16; o > 0; o >>= 1)
            s += __shfl_xor_sync(0xffffffffu, s, o);
        float pv = (s > THR2) ? s : 0.f;
        if (lane == t) pvm = pv;
    }

    unsigned spmask = __ballot_sync(0xffffffffu, (pvm > 0.f) && (lane < T_));
    int nsp = __popc(spmask);
    int ft = T_ - nsp;
    if (ft < 0) ft = 0;
    if (ft > T_ - 1) ft = T_ - 1;
    float fval = __shfl_sync(0xffffffffu, pvm, ft);

    if (lane < T_ && pvm > 0.f) {
        size_t o = ((size_t)lane * F2 + wf) * NHW + hw;
        out[o] = 1.f;
        out[(size_t)T_ * F2 * NHW + o] = pvm;
    }
    if (lane == 0) {
        g_val[hw] = fval;
        g_nsp[hw] = nsp;
        g_wf[hw]  = wf;
        if (nsp > 0) atomicMax(&g_maxbits, __float_as_uint(fval));
    }
}

// ===================== k-WTA =====================
__global__ __launch_bounds__(1024) void winners_k(float* __restrict__ out)
{
    const int tid = threadIdx.x;
    __shared__ unsigned long long sred[32];

    float maxval = __uint_as_float(g_maxbits);
    float v15 = 15.f * maxval;

    float tot[7];
    int key[7], fh[7], hh[7], ww[7];
#pragma unroll
    for (int k = 0; k < 7; k++) {
        int idx = tid + k * 1024;
        if (idx < NHW) {
            int nsp = g_nsp[idx];
            float val = g_val[idx];
            int f = g_wf[idx];
            tot[k] = (nsp > 0) ? (float)nsp * (val + v15) : 0.f;
            fh[k] = f;
            hh[k] = idx / PH;
            ww[k] = idx % PH;
            key[k] = f * NHW + idx;
        } else {
            tot[k] = 0.f; key[k] = 0; fh[k] = -2; hh[k] = -100; ww[k] = -100;
        }
    }

    float* wout = out + (size_t)2 * T_ * F2 * NHW;

    for (int it = 0; it < KWTA; it++) {
        unsigned long long p = 0ull;
#pragma unroll
        for (int k = 0; k < 7; k++) {
            if (tot[k] > 0.f) {
                unsigned long long pk =
                    ((unsigned long long)__float_as_uint(tot[k]) << 32) |
                    (unsigned long long)(0x7FFFFFFFu - (unsigned)key[k]);
                if (pk > p) p = pk;
            }
        }
#pragma unroll
        for (int o = 16; o > 0; o >>= 1) {
            unsigned long long qq = __shfl_down_sync(0xffffffffu, p, o);
            if (qq > p) p = qq;
        }
        int warp = tid >> 5, lane = tid & 31;
        if (lane == 0) sred[warp] = p;
        __syncthreads();
        if (warp == 0) {
            p = (lane < 32) ? sred[lane] : 0ull;
#pragma unroll
            for (int o = 16; o > 0; o >>= 1) {
                unsigned long long qq = __shfl_down_sync(0xffffffffu, p, o);
                if (qq > p) p = qq;
            }
            if (lane == 0) sred[0] = p;
        }
        __syncthreads();
        unsigned long long best = sred[0];
        __syncthreads();

        if ((best >> 32) == 0ull) {
            if (tid == 0) {
                wout[it * 3 + 0] = -1.f;
                wout[it * 3 + 1] = -1.f;
                wout[it * 3 + 2] = -1.f;
            }
            continue;
        }
        int bkey = (int)(0x7FFFFFFFu - (unsigned)(best & 0xFFFFFFFFull));
        int bf = bkey / NHW;
        int bhw = bkey % NHW;
        int bh = bhw / PH, bw = bhw % PH;

        if (tid == 0) {
            wout[it * 3 + 0] = (float)bf;
            wout[it * 3 + 1] = (float)bh;
            wout[it * 3 + 2] = (float)bw;
        }

#pragma unroll
        for (int k = 0; k < 7; k++) {
            int dh = hh[k] - bh; if (dh < 0) dh = -dh;
            int dw = ww[k] - bw; if (dw < 0) dw = -dw;
            if (fh[k] == bf || (dh <= RADIUS && dw <= RADIUS)) tot[k] = 0.f;
        }
    }
}

// ===================== launch =====================
extern "C" void kernel_launch(void* const* d_in, const int* in_sizes, int n_in,
                              void* d_out, int out_size)
{
    const float* data = (const float*)d_in[0];
    const float* W1   = (const float*)d_in[1];
    const float* W2   = (const float*)d_in[2];
    float* out = (float*)d_out;

    cudaFuncSetAttribute(conv1_mma_k, cudaFuncAttributeMaxDynamicSharedMemorySize, SM1_TOTAL);
    cudaFuncSetAttribute(conv2_mma_k, cudaFuncAttributeMaxDynamicSharedMemorySize, SM2_TOTAL);

    prep_k<<<136, 256>>>(W1, W2);

    dim3 g1(200, T_);
    conv1_mma_k<<<g1, 256, SM1_TOTAL>>>(data, out, out_size / 4);

    zero_k<<<(T_ * NHW + 255) / 256, 256>>>();

    dim3 g2(100, T_);
    conv2_mma_k<<<g2, 256, SM2_TOTAL>>>();

    inhib_k<<<(NHW * 32 + 255) / 256, 256>>>(W2, out);

    winners_k<<<1, 1024>>>(out);
}